// round 4
// baseline (speedup 1.0000x reference)
#include <cuda_runtime.h>

#define BB 4
#define SS 2048
#define EE 1024
#define HH 16
#define HD 64
#define NW 8
#define TQ 128
#define CK 256

typedef unsigned long long ull;

__device__ __forceinline__ ull fma2(ull a, ull b, ull c){
    ull d; asm("fma.rn.f32x2 %0, %1, %2, %3;" : "=l"(d) : "l"(a), "l"(b), "l"(c)); return d;
}
__device__ __forceinline__ ull add2(ull a, ull b){
    ull d; asm("add.rn.f32x2 %0, %1, %2;" : "=l"(d) : "l"(a), "l"(b)); return d;
}
__device__ __forceinline__ ull pack2(float lo, float hi){
    ull d; asm("mov.b64 %0, {%1, %2};" : "=l"(d) : "f"(lo), "f"(hi)); return d;
}
__device__ __forceinline__ void unpack2(ull v, float& lo, float& hi){
    asm("mov.b64 {%0, %1}, %2;" : "=f"(lo), "=f"(hi) : "l"(v));
}

// Scratch (static device memory — no allocations)
__device__ __align__(16) float2 g_qo[BB*SS*NW];       // cos(x+theta), duplicated for f32x2
__device__ __align__(16) float  g_qp[EE*NW];
__device__ __align__(16) float  g_kp[EE*NW];
__device__ __align__(16) float  g_vp[EE*NW];
__device__ __align__(16) float  g_M[HH*81];           // per-head 9x9 (augmented, /8 folded)
__device__ __align__(16) float  g_G[HH*NW*EE];        // [128][1024]
__device__ __align__(16) float  g_bias2[EE];          // out_w@v_b + out_b
__device__ __align__(16) float  g_Z[BB*SS*HH*NW];     // [8192][128] normalized z

// ---------------- K1: qo = cos(x[..., :8] + theta), duplicated ----------------
__global__ void k_qo(const float* __restrict__ x, const float* __restrict__ theta){
    int idx = blockIdx.x*blockDim.x + threadIdx.x;
    if (idx >= BB*SS*NW) return;
    int i = idx & 7;
    int row = idx >> 3;
    float v = cosf(x[(size_t)row*EE + i] + theta[i]);
    g_qo[idx] = make_float2(v, v);
}

// ---------------- K2: qp/kp/vp[e][i] = sum_k W[e][k] * proj[k][i] ----------------
__global__ void k_proj(const float* __restrict__ qw, const float* __restrict__ kw,
                       const float* __restrict__ vw, const float* __restrict__ proj){
    int gw = (blockIdx.x*blockDim.x + threadIdx.x) >> 5;
    int lane = threadIdx.x & 31;
    if (gw >= 3*EE) return;
    int mat = gw >> 10;
    int e = gw & 1023;
    const float* W = (mat==0) ? qw : (mat==1 ? kw : vw);
    float acc[8];
    #pragma unroll
    for (int i=0;i<8;i++) acc[i]=0.f;
    for (int k=lane; k<EE; k+=32){
        float wv = W[(size_t)e*EE + k];
        float4 p0 = *(const float4*)(proj + k*8);
        float4 p1 = *(const float4*)(proj + k*8 + 4);
        acc[0] += wv*p0.x; acc[1] += wv*p0.y; acc[2] += wv*p0.z; acc[3] += wv*p0.w;
        acc[4] += wv*p1.x; acc[5] += wv*p1.y; acc[6] += wv*p1.z; acc[7] += wv*p1.w;
    }
    #pragma unroll
    for (int off=16; off; off>>=1){
        #pragma unroll
        for (int i=0;i<8;i++) acc[i] += __shfl_down_sync(0xffffffffu, acc[i], off);
    }
    if (lane==0){
        float* dst = (mat==0 ? g_qp : (mat==1 ? g_kp : g_vp)) + e*8;
        *(float4*)dst     = make_float4(acc[0],acc[1],acc[2],acc[3]);
        *(float4*)(dst+4) = make_float4(acc[4],acc[5],acc[6],acc[7]);
    }
}

// ---------------- K3: per-head augmented 9x9 score matrix ----------------
__global__ void k_M(const float* __restrict__ qb, const float* __restrict__ kb){
    int h = blockIdx.x;
    int t = threadIdx.x;
    if (t >= 81) return;
    int i = t/9, j = t%9;
    float s = 0.f;
    #pragma unroll 8
    for (int d=0; d<HD; d++){
        int r = h*HD + d;
        float a  = (i<8) ? g_qp[r*8+i] : qb[r];
        float bv = (j<8) ? g_kp[r*8+j] : kb[r];
        s += a*bv;
    }
    g_M[h*81+t] = s * 0.125f;   // 1/sqrt(HD)=1/8 folded in
}

// ---------------- K4: G[j=h*8+i][e] = sum_d out_w[e][h*64+d]*vp[h*64+d][i]; bias2 ----------------
__global__ void k_G(const float* __restrict__ ow, const float* __restrict__ vb,
                    const float* __restrict__ ob){
    __shared__ float row[EE];
    __shared__ float pb[128];
    int e = blockIdx.x, tid = threadIdx.x;
    for (int k=tid; k<EE; k+=128) row[k] = ow[(size_t)e*EE + k];
    __syncthreads();
    int h = tid >> 3, i = tid & 7;
    float s = 0.f;
    #pragma unroll 8
    for (int d=0; d<HD; d++) s += row[h*HD+d] * g_vp[(h*HD+d)*8 + i];
    g_G[(size_t)tid*EE + e] = s;
    float bacc = 0.f;
    for (int k=tid; k<EE; k+=128) bacc += row[k]*vb[k];
    pb[tid] = bacc; __syncthreads();
    for (int off=64; off; off>>=1){
        if (tid<off) pb[tid] += pb[tid+off];
        __syncthreads();
    }
    if (tid==0) g_bias2[e] = pb[0] + ob[e];
}

// ---------------- K5: attention in compressed space ----------------
// Per CTA: 64 threads, 2 q-rows each (f32x2-packed), one (b,h,q-block of 128).
__global__ __launch_bounds__(64) void k_attn(){
    __shared__ __align__(16) ull skeys[CK*NW];  // duplicated qo per key (8 x f32x2)
    __shared__ float sM[81];
    int tid = threadIdx.x;
    int b = blockIdx.z, h = blockIdx.y;
    int q0 = blockIdx.x*TQ + tid*2;

    for (int i=tid; i<81; i+=64) sM[i] = g_M[h*81+i];
    __syncthreads();

    float qa[8], qbv[8];
    const float2* r0 = g_qo + (size_t)(b*SS + q0)*NW;
    #pragma unroll
    for (int i=0;i<8;i++){ qa[i]=r0[i].x; qbv[i]=r0[NW+i].x; }

    ull t2[9];
    #pragma unroll
    for (int j=0;j<9;j++){
        float ta = sM[72+j], tb = sM[72+j];
        #pragma unroll
        for (int i=0;i<8;i++){ ta += qa[i]*sM[i*9+j]; tb += qbv[i]*sM[i*9+j]; }
        t2[j] = pack2(ta, tb);
    }

    ull z2[8];
    #pragma unroll
    for (int i=0;i<8;i++) z2[i] = 0ull;
    ull l2 = 0ull;

    const float4* src = (const float4*)(g_qo + (size_t)b*SS*NW);
    for (int c=0; c<SS/CK; c++){
        __syncthreads();
        float4* dst4 = (float4*)skeys;
        const float4* s4 = src + c*(CK*NW/2);
        for (int idx=tid; idx<CK*NW/2; idx+=64) dst4[idx] = s4[idx];
        __syncthreads();
        #pragma unroll 4
        for (int k=0; k<CK; k++){
            const ulonglong2* kp2 = (const ulonglong2*)(skeys + k*NW);
            ulonglong2 k01=kp2[0], k23=kp2[1], k45=kp2[2], k67=kp2[3];
            ull s2 = t2[8];
            s2 = fma2(t2[0], k01.x, s2);
            s2 = fma2(t2[1], k01.y, s2);
            s2 = fma2(t2[2], k23.x, s2);
            s2 = fma2(t2[3], k23.y, s2);
            s2 = fma2(t2[4], k45.x, s2);
            s2 = fma2(t2[5], k45.y, s2);
            s2 = fma2(t2[6], k67.x, s2);
            s2 = fma2(t2[7], k67.y, s2);
            float sa, sb; unpack2(s2, sa, sb);
            ull p2 = pack2(__expf(sa), __expf(sb));   // scores small; no max-sub needed
            l2 = add2(l2, p2);
            z2[0]=fma2(p2,k01.x,z2[0]); z2[1]=fma2(p2,k01.y,z2[1]);
            z2[2]=fma2(p2,k23.x,z2[2]); z2[3]=fma2(p2,k23.y,z2[3]);
            z2[4]=fma2(p2,k45.x,z2[4]); z2[5]=fma2(p2,k45.y,z2[5]);
            z2[6]=fma2(p2,k67.x,z2[6]); z2[7]=fma2(p2,k67.y,z2[7]);
        }
    }

    float la, lb; unpack2(l2, la, lb);
    float ia = 1.0f/la, ib = 1.0f/lb;
    float oa[8], ob_[8];
    #pragma unroll
    for (int i=0;i<8;i++){
        float za, zb; unpack2(z2[i], za, zb);
        oa[i] = za*ia; ob_[i] = zb*ib;
    }
    float* d0 = g_Z + (size_t)(b*SS+q0)*(HH*NW) + h*NW;
    *(float4*)(d0)   = make_float4(oa[0],oa[1],oa[2],oa[3]);
    *(float4*)(d0+4) = make_float4(oa[4],oa[5],oa[6],oa[7]);
    float* d1 = d0 + HH*NW;
    *(float4*)(d1)   = make_float4(ob_[0],ob_[1],ob_[2],ob_[3]);
    *(float4*)(d1+4) = make_float4(ob_[4],ob_[5],ob_[6],ob_[7]);
}

// ---------------- K6: out = Z @ G^T + bias2 ----------------
// 64x64 output tile per CTA, K=128 in two 64-chunks, f32x2 over row pairs.
__global__ __launch_bounds__(256) void k_out(float* __restrict__ out){
    __shared__ __align__(16) float Zt[64*66];   // [k][66-pad]: Zt[k][r]
    __shared__ __align__(16) float Gs[64*64];   // [j][c]
    int tid = threadIdx.x;
    int row0 = blockIdx.x*64;
    int col0 = blockIdx.y*64;
    int rp = tid & 31, cg = tid >> 5;

    ull a0[4], a1[4];
    #pragma unroll
    for (int m=0;m<4;m++){ a0[m]=0ull; a1[m]=0ull; }

    for (int kk=0; kk<2; kk++){
        __syncthreads();
        for (int idx=tid; idx<4096; idx+=256){
            int k = idx & 63, r = idx >> 6;
            Zt[k*66 + r] = g_Z[(size_t)(row0+r)*(HH*NW) + kk*64 + k];
        }
        for (int idx=tid; idx<4096; idx+=256){
            int c = idx & 63, j = idx >> 6;
            Gs[j*64 + c] = g_G[(size_t)(kk*64+j)*EE + col0 + c];
        }
        __syncthreads();
        #pragma unroll 16
        for (int k=0; k<64; k++){
            float2 zz = *(const float2*)&Zt[k*66 + rp*2];
            const ulonglong2* g2 = (const ulonglong2*)&Gs[k*64 + cg*8];
            ulonglong2 gA = g2[0], gB = g2[1];
            ull dA = pack2(zz.x, zz.x);
            ull dB = pack2(zz.y, zz.y);
            a0[0]=fma2(dA,gA.x,a0[0]); a0[1]=fma2(dA,gA.y,a0[1]);
            a0[2]=fma2(dA,gB.x,a0[2]); a0[3]=fma2(dA,gB.y,a0[3]);
            a1[0]=fma2(dB,gA.x,a1[0]); a1[1]=fma2(dB,gA.y,a1[1]);
            a1[2]=fma2(dB,gB.x,a1[2]); a1[3]=fma2(dB,gB.y,a1[3]);
        }
    }

    int col = col0 + cg*8;
    const float* bz = g_bias2 + col;
    ull b01 = pack2(bz[0],bz[1]), b23 = pack2(bz[2],bz[3]);
    ull b45 = pack2(bz[4],bz[5]), b67 = pack2(bz[6],bz[7]);
    a0[0]=add2(a0[0],b01); a0[1]=add2(a0[1],b23);
    a0[2]=add2(a0[2],b45); a0[3]=add2(a0[3],b67);
    a1[0]=add2(a1[0],b01); a1[1]=add2(a1[1],b23);
    a1[2]=add2(a1[2],b45); a1[3]=add2(a1[3],b67);

    int r0 = row0 + rp*2;
    float* o0 = out + (size_t)r0*EE + col;
    ulonglong2 s01; s01.x=a0[0]; s01.y=a0[1]; *(ulonglong2*)o0 = s01;
    ulonglong2 s23; s23.x=a0[2]; s23.y=a0[3]; *((ulonglong2*)o0 + 1) = s23;
    float* o1 = o0 + EE;
    ulonglong2 t01; t01.x=a1[0]; t01.y=a1[1]; *(ulonglong2*)o1 = t01;
    ulonglong2 t23; t23.x=a1[2]; t23.y=a1[3]; *((ulonglong2*)o1 + 1) = t23;
}

extern "C" void kernel_launch(void* const* d_in, const int* in_sizes, int n_in,
                              void* d_out, int out_size){
    (void)in_sizes; (void)n_in; (void)out_size;
    const float* x     = (const float*)d_in[0];
    const float* theta = (const float*)d_in[1];
    const float* proj  = (const float*)d_in[2];
    const float* qw    = (const float*)d_in[3];
    const float* qb    = (const float*)d_in[4];
    const float* kw    = (const float*)d_in[5];
    const float* kb    = (const float*)d_in[6];
    const float* vw    = (const float*)d_in[7];
    const float* vb    = (const float*)d_in[8];
    const float* ow    = (const float*)d_in[9];
    const float* ob    = (const float*)d_in[10];
    float* out = (float*)d_out;

    k_qo  <<<(BB*SS*NW + 255)/256, 256>>>(x, theta);
    k_proj<<<(3*EE*32 + 255)/256, 256>>>(qw, kw, vw, proj);
    k_M   <<<HH, 96>>>(qb, kb);
    k_G   <<<EE, 128>>>(ow, vb, ob);
    k_attn<<<dim3(SS/TQ, HH, BB), 64>>>();
    k_out <<<dim3(BB*SS/64, EE/64), 256>>>(out);
}

// round 5
// speedup vs baseline: 1.0795x; 1.0795x over previous
#include <cuda_runtime.h>

#define BB 4
#define SS 2048
#define EE 1024
#define HH 16
#define HD 64
#define NW 8
#define TQ 256
#define CK 256

typedef unsigned long long ull;

__device__ __forceinline__ ull fma2(ull a, ull b, ull c){
    ull d; asm("fma.rn.f32x2 %0, %1, %2, %3;" : "=l"(d) : "l"(a), "l"(b), "l"(c)); return d;
}
__device__ __forceinline__ ull add2(ull a, ull b){
    ull d; asm("add.rn.f32x2 %0, %1, %2;" : "=l"(d) : "l"(a), "l"(b)); return d;
}
__device__ __forceinline__ ull pack2(float lo, float hi){
    ull d; asm("mov.b64 %0, {%1, %2};" : "=l"(d) : "f"(lo), "f"(hi)); return d;
}
__device__ __forceinline__ void unpack2(ull v, float& lo, float& hi){
    asm("mov.b64 {%0, %1}, %2;" : "=f"(lo), "=f"(hi) : "l"(v));
}
__device__ __forceinline__ float ex2f(float x){
    float y; asm("ex2.approx.f32 %0, %1;" : "=f"(y) : "f"(x)); return y;
}

// Scratch (static device memory — no allocations)
__device__ __align__(16) float2 g_qo[BB*SS*NW];       // cos(x+theta), duplicated for f32x2
__device__ __align__(16) float  g_qp[EE*NW];
__device__ __align__(16) float  g_kp[EE*NW];
__device__ __align__(16) float  g_vp[EE*NW];
__device__ __align__(16) float  g_M[HH*81];           // per-head 9x9 (log2e/8 folded)
__device__ __align__(16) float  g_G[HH*NW*EE];        // [128][1024]
__device__ __align__(16) float  g_bias2[EE];          // out_w@v_b + out_b
__device__ __align__(16) float  g_Z[BB*SS*HH*NW];     // [8192][128] normalized z

// ---------------- K1: qo = cos(x[..., :8] + theta), duplicated ----------------
__global__ void k_qo(const float* __restrict__ x, const float* __restrict__ theta){
    int idx = blockIdx.x*blockDim.x + threadIdx.x;
    if (idx >= BB*SS*NW) return;
    int i = idx & 7;
    int row = idx >> 3;
    float v = cosf(x[(size_t)row*EE + i] + theta[i]);
    g_qo[idx] = make_float2(v, v);
}

// ---------------- K2: qp/kp/vp[e][i] = sum_k W[e][k] * proj[k][i] ----------------
__global__ void k_proj(const float* __restrict__ qw, const float* __restrict__ kw,
                       const float* __restrict__ vw, const float* __restrict__ proj){
    int gw = (blockIdx.x*blockDim.x + threadIdx.x) >> 5;
    int lane = threadIdx.x & 31;
    if (gw >= 3*EE) return;
    int mat = gw >> 10;
    int e = gw & 1023;
    const float* W = (mat==0) ? qw : (mat==1 ? kw : vw);
    float acc[8];
    #pragma unroll
    for (int i=0;i<8;i++) acc[i]=0.f;
    for (int k=lane; k<EE; k+=32){
        float wv = W[(size_t)e*EE + k];
        float4 p0 = *(const float4*)(proj + k*8);
        float4 p1 = *(const float4*)(proj + k*8 + 4);
        acc[0] += wv*p0.x; acc[1] += wv*p0.y; acc[2] += wv*p0.z; acc[3] += wv*p0.w;
        acc[4] += wv*p1.x; acc[5] += wv*p1.y; acc[6] += wv*p1.z; acc[7] += wv*p1.w;
    }
    #pragma unroll
    for (int off=16; off; off>>=1){
        #pragma unroll
        for (int i=0;i<8;i++) acc[i] += __shfl_down_sync(0xffffffffu, acc[i], off);
    }
    if (lane==0){
        float* dst = (mat==0 ? g_qp : (mat==1 ? g_kp : g_vp)) + e*8;
        *(float4*)dst     = make_float4(acc[0],acc[1],acc[2],acc[3]);
        *(float4*)(dst+4) = make_float4(acc[4],acc[5],acc[6],acc[7]);
    }
}

// ---------------- K3: per-head augmented 9x9 score matrix (log2e * 1/8 folded) ----------------
__global__ void k_M(const float* __restrict__ qb, const float* __restrict__ kb){
    int h = blockIdx.x;
    int t = threadIdx.x;
    if (t >= 81) return;
    int i = t/9, j = t%9;
    float s = 0.f;
    #pragma unroll 8
    for (int d=0; d<HD; d++){
        int r = h*HD + d;
        float a  = (i<8) ? g_qp[r*8+i] : qb[r];
        float bv = (j<8) ? g_kp[r*8+j] : kb[r];
        s += a*bv;
    }
    // 1/sqrt(HD)=0.125 and log2(e) folded in; scores computed in log2-space, exp via ex2
    g_M[h*81+t] = s * 0.125f * 1.4426950408889634f;
}

// ---------------- K4: G[j=h*8+i][e] = sum_d out_w[e][h*64+d]*vp[h*64+d][i]; bias2 ----------------
__global__ void k_G(const float* __restrict__ ow, const float* __restrict__ vb,
                    const float* __restrict__ ob){
    __shared__ __align__(16) float row[EE];
    __shared__ float pb[128];
    int e = blockIdx.x, tid = threadIdx.x;
    const float4* src4 = (const float4*)(ow + (size_t)e*EE);
    float4* row4 = (float4*)row;
    #pragma unroll
    for (int k=tid; k<EE/4; k+=128) row4[k] = src4[k];
    __syncthreads();
    int h = tid >> 3, i = tid & 7;
    float s = 0.f;
    #pragma unroll 8
    for (int d=0; d<HD; d++) s += row[h*HD+d] * g_vp[(h*HD+d)*8 + i];
    g_G[(size_t)tid*EE + e] = s;
    float bacc = 0.f;
    for (int k=tid; k<EE; k+=128) bacc += row[k]*vb[k];
    pb[tid] = bacc; __syncthreads();
    for (int off=64; off; off>>=1){
        if (tid<off) pb[tid] += pb[tid+off];
        __syncthreads();
    }
    if (tid==0) g_bias2[e] = pb[0] + ob[e];
}

// ---------------- K5: attention in compressed space ----------------
// Per CTA: 64 threads, 4 q-rows each (2 f32x2 pairs) — key LDS amortized over 4 rows.
__global__ __launch_bounds__(64) void k_attn(){
    __shared__ __align__(16) ull skeys[CK*NW];  // duplicated qo per key (8 x f32x2)
    __shared__ float sM[81];
    int tid = threadIdx.x;
    int b = blockIdx.z, h = blockIdx.y;
    int q0 = blockIdx.x*TQ + tid*4;

    for (int i=tid; i<81; i+=64) sM[i] = g_M[h*81+i];
    __syncthreads();

    // Load 4 query rows
    float qv[4][8];
    const float2* r0 = g_qo + (size_t)(b*SS + q0)*NW;
    #pragma unroll
    for (int j=0;j<4;j++)
        #pragma unroll
        for (int i=0;i<8;i++) qv[j][i] = r0[j*NW+i].x;

    // Transformed queries: t2[pair][j] packs (row 2p, row 2p+1)
    ull t2[2][9];
    #pragma unroll
    for (int p=0;p<2;p++)
        #pragma unroll
        for (int j=0;j<9;j++){
            float ta = sM[72+j], tb = sM[72+j];
            #pragma unroll
            for (int i=0;i<8;i++){ ta += qv[2*p][i]*sM[i*9+j]; tb += qv[2*p+1][i]*sM[i*9+j]; }
            t2[p][j] = pack2(ta, tb);
        }

    ull z2[2][8];
    ull l2[2];
    #pragma unroll
    for (int p=0;p<2;p++){
        l2[p] = 0ull;
        #pragma unroll
        for (int i=0;i<8;i++) z2[p][i] = 0ull;
    }

    const float4* src = (const float4*)(g_qo + (size_t)b*SS*NW);
    for (int c=0; c<SS/CK; c++){
        __syncthreads();
        float4* dst4 = (float4*)skeys;
        const float4* s4 = src + c*(CK*NW/2);
        #pragma unroll 4
        for (int idx=tid; idx<CK*NW/2; idx+=64) dst4[idx] = s4[idx];
        __syncthreads();
        #pragma unroll 2
        for (int k=0; k<CK; k++){
            const ulonglong2* kp2 = (const ulonglong2*)(skeys + k*NW);
            ulonglong2 k01=kp2[0], k23=kp2[1], k45=kp2[2], k67=kp2[3];
            #pragma unroll
            for (int p=0;p<2;p++){
                ull s2 = t2[p][8];
                s2 = fma2(t2[p][0], k01.x, s2);
                s2 = fma2(t2[p][1], k01.y, s2);
                s2 = fma2(t2[p][2], k23.x, s2);
                s2 = fma2(t2[p][3], k23.y, s2);
                s2 = fma2(t2[p][4], k45.x, s2);
                s2 = fma2(t2[p][5], k45.y, s2);
                s2 = fma2(t2[p][6], k67.x, s2);
                s2 = fma2(t2[p][7], k67.y, s2);
                float sa, sb; unpack2(s2, sa, sb);
                ull p2 = pack2(ex2f(sa), ex2f(sb));   // scores are log2-scaled; small, no max-sub
                l2[p] = add2(l2[p], p2);
                z2[p][0]=fma2(p2,k01.x,z2[p][0]); z2[p][1]=fma2(p2,k01.y,z2[p][1]);
                z2[p][2]=fma2(p2,k23.x,z2[p][2]); z2[p][3]=fma2(p2,k23.y,z2[p][3]);
                z2[p][4]=fma2(p2,k45.x,z2[p][4]); z2[p][5]=fma2(p2,k45.y,z2[p][5]);
                z2[p][6]=fma2(p2,k67.x,z2[p][6]); z2[p][7]=fma2(p2,k67.y,z2[p][7]);
            }
        }
    }

    #pragma unroll
    for (int p=0;p<2;p++){
        float la, lb; unpack2(l2[p], la, lb);
        float ia = 1.0f/la, ib = 1.0f/lb;
        float oa[8], obv[8];
        #pragma unroll
        for (int i=0;i<8;i++){
            float za, zb; unpack2(z2[p][i], za, zb);
            oa[i] = za*ia; obv[i] = zb*ib;
        }
        float* d0 = g_Z + (size_t)(b*SS + q0 + 2*p)*(HH*NW) + h*NW;
        *(float4*)(d0)   = make_float4(oa[0],oa[1],oa[2],oa[3]);
        *(float4*)(d0+4) = make_float4(oa[4],oa[5],oa[6],oa[7]);
        float* d1 = d0 + HH*NW;
        *(float4*)(d1)   = make_float4(obv[0],obv[1],obv[2],obv[3]);
        *(float4*)(d1+4) = make_float4(obv[4],obv[5],obv[6],obv[7]);
    }
}

// ---------------- K6: out = Z @ G^T + bias2 ----------------
// 64x64 output tile per CTA, K=128 in two 64-chunks, f32x2 over row pairs.
__global__ __launch_bounds__(256) void k_out(float* __restrict__ out){
    __shared__ __align__(16) float Zt[64*66];   // [k][66-pad]: Zt[k][r]
    __shared__ __align__(16) float Gs[64*64];   // [j][c]
    int tid = threadIdx.x;
    int row0 = blockIdx.x*64;
    int col0 = blockIdx.y*64;
    int rp = tid & 31, cg = tid >> 5;

    ull a0[4], a1[4];
    #pragma unroll
    for (int m=0;m<4;m++){ a0[m]=0ull; a1[m]=0ull; }

    for (int kk=0; kk<2; kk++){
        __syncthreads();
        for (int idx=tid; idx<4096; idx+=256){
            int k = idx & 63, r = idx >> 6;
            Zt[k*66 + r] = g_Z[(size_t)(row0+r)*(HH*NW) + kk*64 + k];
        }
        for (int idx=tid; idx<4096; idx+=256){
            int c = idx & 63, j = idx >> 6;
            Gs[j*64 + c] = g_G[(size_t)(kk*64+j)*EE + col0 + c];
        }
        __syncthreads();
        #pragma unroll 16
        for (int k=0; k<64; k++){
            float2 zz = *(const float2*)&Zt[k*66 + rp*2];
            const ulonglong2* g2 = (const ulonglong2*)&Gs[k*64 + cg*8];
            ulonglong2 gA = g2[0], gB = g2[1];
            ull dA = pack2(zz.x, zz.x);
            ull dB = pack2(zz.y, zz.y);
            a0[0]=fma2(dA,gA.x,a0[0]); a0[1]=fma2(dA,gA.y,a0[1]);
            a0[2]=fma2(dA,gB.x,a0[2]); a0[3]=fma2(dA,gB.y,a0[3]);
            a1[0]=fma2(dB,gA.x,a1[0]); a1[1]=fma2(dB,gA.y,a1[1]);
            a1[2]=fma2(dB,gB.x,a1[2]); a1[3]=fma2(dB,gB.y,a1[3]);
        }
    }

    int col = col0 + cg*8;
    const float* bz = g_bias2 + col;
    ull b01 = pack2(bz[0],bz[1]), b23 = pack2(bz[2],bz[3]);
    ull b45 = pack2(bz[4],bz[5]), b67 = pack2(bz[6],bz[7]);
    a0[0]=add2(a0[0],b01); a0[1]=add2(a0[1],b23);
    a0[2]=add2(a0[2],b45); a0[3]=add2(a0[3],b67);
    a1[0]=add2(a1[0],b01); a1[1]=add2(a1[1],b23);
    a1[2]=add2(a1[2],b45); a1[3]=add2(a1[3],b67);

    int r0 = row0 + rp*2;
    float* o0 = out + (size_t)r0*EE + col;
    ulonglong2 s01; s01.x=a0[0]; s01.y=a0[1]; *(ulonglong2*)o0 = s01;
    ulonglong2 s23; s23.x=a0[2]; s23.y=a0[3]; *((ulonglong2*)o0 + 1) = s23;
    float* o1 = o0 + EE;
    ulonglong2 t01; t01.x=a1[0]; t01.y=a1[1]; *(ulonglong2*)o1 = t01;
    ulonglong2 t23; t23.x=a1[2]; t23.y=a1[3]; *((ulonglong2*)o1 + 1) = t23;
}

extern "C" void kernel_launch(void* const* d_in, const int* in_sizes, int n_in,
                              void* d_out, int out_size){
    (void)in_sizes; (void)n_in; (void)out_size;
    const float* x     = (const float*)d_in[0];
    const float* theta = (const float*)d_in[1];
    const float* proj  = (const float*)d_in[2];
    const float* qw    = (const float*)d_in[3];
    const float* qb    = (const float*)d_in[4];
    const float* kw    = (const float*)d_in[5];
    const float* kb    = (const float*)d_in[6];
    const float* vw    = (const float*)d_in[7];
    const float* vb    = (const float*)d_in[8];
    const float* ow    = (const float*)d_in[9];
    const float* ob    = (const float*)d_in[10];
    float* out = (float*)d_out;

    k_qo  <<<(BB*SS*NW + 255)/256, 256>>>(x, theta);
    k_proj<<<(3*EE*32 + 255)/256, 256>>>(qw, kw, vw, proj);
    k_M   <<<HH, 96>>>(qb, kb);
    k_G   <<<EE, 128>>>(ow, vb, ob);
    k_attn<<<dim3(SS/TQ, HH, BB), 64>>>();
    k_out <<<dim3(BB*SS/64, EE/64), 256>>>(out);
}

// round 6
// speedup vs baseline: 1.1395x; 1.0556x over previous
#include <cuda_runtime.h>

#define BB 4
#define SS 2048
#define EE 1024
#define HH 16
#define HD 64
#define NW 8
#define TQ 256
#define CK 256
#define SPL 4
#define KPC (SS/SPL)

typedef unsigned long long ull;

__device__ __forceinline__ ull fma2(ull a, ull b, ull c){
    ull d; asm("fma.rn.f32x2 %0, %1, %2, %3;" : "=l"(d) : "l"(a), "l"(b), "l"(c)); return d;
}
__device__ __forceinline__ ull add2(ull a, ull b){
    ull d; asm("add.rn.f32x2 %0, %1, %2;" : "=l"(d) : "l"(a), "l"(b)); return d;
}
__device__ __forceinline__ ull pack2(float lo, float hi){
    ull d; asm("mov.b64 %0, {%1, %2};" : "=l"(d) : "f"(lo), "f"(hi)); return d;
}
__device__ __forceinline__ void unpack2(ull v, float& lo, float& hi){
    asm("mov.b64 {%0, %1}, %2;" : "=f"(lo), "=f"(hi) : "l"(v));
}
__device__ __forceinline__ float ex2f(float x){
    float y; asm("ex2.approx.f32 %0, %1;" : "=f"(y) : "f"(x)); return y;
}

// Scratch (static device memory — no allocations)
__device__ __align__(16) float2 g_qo[BB*SS*NW];       // cos(x+theta), duplicated for f32x2
__device__ __align__(16) float  g_qp[EE*NW];
__device__ __align__(16) float  g_kp[EE*NW];
__device__ __align__(16) float  g_vp[EE*NW];
__device__ __align__(16) float  g_M[HH*81];           // per-head 9x9 (log2e/8 folded)
__device__ __align__(16) float  g_G[HH*NW*EE];        // [128][1024]
__device__ __align__(16) float  g_bias2[EE];          // out_w@v_b + out_b
__device__ __align__(16) float  g_Z[BB*SS*HH*NW];     // [8192][128] normalized z
__device__ __align__(16) float  g_Zp[BB*SS*HH*SPL*NW];// [row][h][split][8] unnormalized partials
__device__ __align__(16) float  g_Lp[BB*SS*HH*SPL];   // [row][h][split] partial denominators

// ---------------- K1: qo = cos(x[..., :8] + theta), duplicated ----------------
__global__ void k_qo(const float* __restrict__ x, const float* __restrict__ theta){
    int idx = blockIdx.x*blockDim.x + threadIdx.x;
    if (idx >= BB*SS*NW) return;
    int i = idx & 7;
    int row = idx >> 3;
    float v = cosf(x[(size_t)row*EE + i] + theta[i]);
    g_qo[idx] = make_float2(v, v);
}

// ---------------- K2: qp/kp/vp[e][i] = sum_k W[e][k] * proj[k][i] ----------------
__global__ void k_proj(const float* __restrict__ qw, const float* __restrict__ kw,
                       const float* __restrict__ vw, const float* __restrict__ proj){
    int gw = (blockIdx.x*blockDim.x + threadIdx.x) >> 5;
    int lane = threadIdx.x & 31;
    if (gw >= 3*EE) return;
    int mat = gw >> 10;
    int e = gw & 1023;
    const float* W = (mat==0) ? qw : (mat==1 ? kw : vw);
    float acc[8];
    #pragma unroll
    for (int i=0;i<8;i++) acc[i]=0.f;
    for (int k=lane; k<EE; k+=32){
        float wv = W[(size_t)e*EE + k];
        float4 p0 = *(const float4*)(proj + k*8);
        float4 p1 = *(const float4*)(proj + k*8 + 4);
        acc[0] += wv*p0.x; acc[1] += wv*p0.y; acc[2] += wv*p0.z; acc[3] += wv*p0.w;
        acc[4] += wv*p1.x; acc[5] += wv*p1.y; acc[6] += wv*p1.z; acc[7] += wv*p1.w;
    }
    #pragma unroll
    for (int off=16; off; off>>=1){
        #pragma unroll
        for (int i=0;i<8;i++) acc[i] += __shfl_down_sync(0xffffffffu, acc[i], off);
    }
    if (lane==0){
        float* dst = (mat==0 ? g_qp : (mat==1 ? g_kp : g_vp)) + e*8;
        *(float4*)dst     = make_float4(acc[0],acc[1],acc[2],acc[3]);
        *(float4*)(dst+4) = make_float4(acc[4],acc[5],acc[6],acc[7]);
    }
}

// ---------------- K3: per-head augmented 9x9 score matrix (log2e * 1/8 folded) ----------------
__global__ void k_M(const float* __restrict__ qb, const float* __restrict__ kb){
    int h = blockIdx.x;
    int t = threadIdx.x;
    if (t >= 81) return;
    int i = t/9, j = t%9;
    float s = 0.f;
    #pragma unroll 8
    for (int d=0; d<HD; d++){
        int r = h*HD + d;
        float a  = (i<8) ? g_qp[r*8+i] : qb[r];
        float bv = (j<8) ? g_kp[r*8+j] : kb[r];
        s += a*bv;
    }
    g_M[h*81+t] = s * 0.125f * 1.4426950408889634f;
}

// ---------------- K4: G[j=h*8+i][e] = sum_d out_w[e][h*64+d]*vp[h*64+d][i]; bias2 ----------------
__global__ void k_G(const float* __restrict__ ow, const float* __restrict__ vb,
                    const float* __restrict__ ob){
    __shared__ __align__(16) float row[EE];
    __shared__ float pb[128];
    int e = blockIdx.x, tid = threadIdx.x;
    const float4* src4 = (const float4*)(ow + (size_t)e*EE);
    float4* row4 = (float4*)row;
    #pragma unroll
    for (int k=tid; k<EE/4; k+=128) row4[k] = src4[k];
    __syncthreads();
    int h = tid >> 3, i = tid & 7;
    float s = 0.f;
    #pragma unroll 8
    for (int d=0; d<HD; d++) s += row[h*HD+d] * g_vp[(h*HD+d)*8 + i];
    g_G[(size_t)tid*EE + e] = s;
    float bacc = 0.f;
    for (int k=tid; k<EE; k+=128) bacc += row[k]*vb[k];
    pb[tid] = bacc; __syncthreads();
    for (int off=64; off; off>>=1){
        if (tid<off) pb[tid] += pb[tid+off];
        __syncthreads();
    }
    if (tid==0) g_bias2[e] = pb[0] + ob[e];
}

// ---------------- K5: attention in compressed space, key-split 4x ----------------
// Per CTA: 64 threads, 4 q-rows each; this CTA covers 512 keys (one split).
__global__ __launch_bounds__(64) void k_attn(){
    __shared__ __align__(16) ull skeys[CK*NW];  // duplicated qo per key (8 x f32x2)
    __shared__ float sM[81];
    int tid = threadIdx.x;
    int bz = blockIdx.z;
    int b = bz >> 2;           // batch
    int half = bz & 3;         // key split index
    int h = blockIdx.y;
    int q0 = blockIdx.x*TQ + tid*4;

    for (int i=tid; i<81; i+=64) sM[i] = g_M[h*81+i];
    __syncthreads();

    // Load 4 query rows
    float qv[4][8];
    const float2* r0 = g_qo + (size_t)(b*SS + q0)*NW;
    #pragma unroll
    for (int j=0;j<4;j++)
        #pragma unroll
        for (int i=0;i<8;i++) qv[j][i] = r0[j*NW+i].x;

    // Transformed queries: t2[pair][j] packs (row 2p, row 2p+1)
    ull t2[2][9];
    #pragma unroll
    for (int p=0;p<2;p++)
        #pragma unroll
        for (int j=0;j<9;j++){
            float ta = sM[72+j], tb = sM[72+j];
            #pragma unroll
            for (int i=0;i<8;i++){ ta += qv[2*p][i]*sM[i*9+j]; tb += qv[2*p+1][i]*sM[i*9+j]; }
            t2[p][j] = pack2(ta, tb);
        }

    ull z2[2][8];
    ull l2[2];
    #pragma unroll
    for (int p=0;p<2;p++){
        l2[p] = 0ull;
        #pragma unroll
        for (int i=0;i<8;i++) z2[p][i] = 0ull;
    }

    const float4* src = (const float4*)(g_qo + (size_t)b*SS*NW) + (size_t)half*(KPC*NW/2);
    for (int c=0; c<KPC/CK; c++){
        __syncthreads();
        float4* dst4 = (float4*)skeys;
        const float4* s4 = src + c*(CK*NW/2);
        #pragma unroll 4
        for (int idx=tid; idx<CK*NW/2; idx+=64) dst4[idx] = s4[idx];
        __syncthreads();
        #pragma unroll 2
        for (int k=0; k<CK; k++){
            const ulonglong2* kp2 = (const ulonglong2*)(skeys + k*NW);
            ulonglong2 k01=kp2[0], k23=kp2[1], k45=kp2[2], k67=kp2[3];
            #pragma unroll
            for (int p=0;p<2;p++){
                ull s2 = t2[p][8];
                s2 = fma2(t2[p][0], k01.x, s2);
                s2 = fma2(t2[p][1], k01.y, s2);
                s2 = fma2(t2[p][2], k23.x, s2);
                s2 = fma2(t2[p][3], k23.y, s2);
                s2 = fma2(t2[p][4], k45.x, s2);
                s2 = fma2(t2[p][5], k45.y, s2);
                s2 = fma2(t2[p][6], k67.x, s2);
                s2 = fma2(t2[p][7], k67.y, s2);
                float sa, sb; unpack2(s2, sa, sb);
                ull p2 = pack2(ex2f(sa), ex2f(sb));   // log2-scaled scores; small, no max-sub
                l2[p] = add2(l2[p], p2);
                z2[p][0]=fma2(p2,k01.x,z2[p][0]); z2[p][1]=fma2(p2,k01.y,z2[p][1]);
                z2[p][2]=fma2(p2,k23.x,z2[p][2]); z2[p][3]=fma2(p2,k23.y,z2[p][3]);
                z2[p][4]=fma2(p2,k45.x,z2[p][4]); z2[p][5]=fma2(p2,k45.y,z2[p][5]);
                z2[p][6]=fma2(p2,k67.x,z2[p][6]); z2[p][7]=fma2(p2,k67.y,z2[p][7]);
            }
        }
    }

    // Write unnormalized partials: g_Zp[row][h][split][8], g_Lp[row][h][split]
    #pragma unroll
    for (int p=0;p<2;p++){
        float la, lb; unpack2(l2[p], la, lb);
        float oa[8], obv[8];
        #pragma unroll
        for (int i=0;i<8;i++){
            float za, zb; unpack2(z2[p][i], za, zb);
            oa[i] = za; obv[i] = zb;
        }
        size_t r0i = (size_t)(b*SS + q0 + 2*p);
        float* d0 = g_Zp + ((r0i*HH + h)*SPL + half)*NW;
        *(float4*)(d0)   = make_float4(oa[0],oa[1],oa[2],oa[3]);
        *(float4*)(d0+4) = make_float4(oa[4],oa[5],oa[6],oa[7]);
        float* d1 = d0 + (size_t)HH*SPL*NW;
        *(float4*)(d1)   = make_float4(obv[0],obv[1],obv[2],obv[3]);
        *(float4*)(d1+4) = make_float4(obv[4],obv[5],obv[6],obv[7]);
        g_Lp[(r0i*HH + h)*SPL + half] = la;
        g_Lp[((r0i+1)*HH + h)*SPL + half] = lb;
    }
}

// ---------------- K5b: reduce partials, normalize -> g_Z ----------------
__global__ void k_red(){
    int t = blockIdx.x*blockDim.x + threadIdx.x;   // (row*HH + h)
    if (t >= BB*SS*HH) return;
    const float4* zp = (const float4*)(g_Zp + (size_t)t*SPL*NW);
    float4 a0 = zp[0], a1 = zp[1];
    #pragma unroll
    for (int s=1;s<SPL;s++){
        float4 b0 = zp[2*s], b1 = zp[2*s+1];
        a0.x+=b0.x; a0.y+=b0.y; a0.z+=b0.z; a0.w+=b0.w;
        a1.x+=b1.x; a1.y+=b1.y; a1.z+=b1.z; a1.w+=b1.w;
    }
    float4 lv = *(const float4*)(g_Lp + (size_t)t*SPL);
    float inv = 1.0f/(lv.x+lv.y+lv.z+lv.w);
    a0.x*=inv; a0.y*=inv; a0.z*=inv; a0.w*=inv;
    a1.x*=inv; a1.y*=inv; a1.z*=inv; a1.w*=inv;
    int row = t >> 4, h = t & 15;
    float* dst = g_Z + (size_t)row*(HH*NW) + h*NW;
    *(float4*)dst     = a0;
    *(float4*)(dst+4) = a1;
}

// ---------------- K6: out = Z @ G^T + bias2 ----------------
__global__ __launch_bounds__(256) void k_out(float* __restrict__ out){
    __shared__ __align__(16) float Zt[64*66];   // [k][66-pad]: Zt[k][r]
    __shared__ __align__(16) float Gs[64*64];   // [j][c]
    int tid = threadIdx.x;
    int row0 = blockIdx.x*64;
    int col0 = blockIdx.y*64;
    int rp = tid & 31, cg = tid >> 5;

    ull a0[4], a1[4];
    #pragma unroll
    for (int m=0;m<4;m++){ a0[m]=0ull; a1[m]=0ull; }

    for (int kk=0; kk<2; kk++){
        __syncthreads();
        for (int idx=tid; idx<4096; idx+=256){
            int k = idx & 63, r = idx >> 6;
            Zt[k*66 + r] = g_Z[(size_t)(row0+r)*(HH*NW) + kk*64 + k];
        }
        for (int idx=tid; idx<4096; idx+=256){
            int c = idx & 63, j = idx >> 6;
            Gs[j*64 + c] = g_G[(size_t)(kk*64+j)*EE + col0 + c];
        }
        __syncthreads();
        #pragma unroll 16
        for (int k=0; k<64; k++){
            float2 zz = *(const float2*)&Zt[k*66 + rp*2];
            const ulonglong2* g2 = (const ulonglong2*)&Gs[k*64 + cg*8];
            ulonglong2 gA = g2[0], gB = g2[1];
            ull dA = pack2(zz.x, zz.x);
            ull dB = pack2(zz.y, zz.y);
            a0[0]=fma2(dA,gA.x,a0[0]); a0[1]=fma2(dA,gA.y,a0[1]);
            a0[2]=fma2(dA,gB.x,a0[2]); a0[3]=fma2(dA,gB.y,a0[3]);
            a1[0]=fma2(dB,gA.x,a1[0]); a1[1]=fma2(dB,gA.y,a1[1]);
            a1[2]=fma2(dB,gB.x,a1[2]); a1[3]=fma2(dB,gB.y,a1[3]);
        }
    }

    int col = col0 + cg*8;
    const float* bz = g_bias2 + col;
    ull b01 = pack2(bz[0],bz[1]), b23 = pack2(bz[2],bz[3]);
    ull b45 = pack2(bz[4],bz[5]), b67 = pack2(bz[6],bz[7]);
    a0[0]=add2(a0[0],b01); a0[1]=add2(a0[1],b23);
    a0[2]=add2(a0[2],b45); a0[3]=add2(a0[3],b67);
    a1[0]=add2(a1[0],b01); a1[1]=add2(a1[1],b23);
    a1[2]=add2(a1[2],b45); a1[3]=add2(a1[3],b67);

    int r0 = row0 + rp*2;
    float* o0 = out + (size_t)r0*EE + col;
    ulonglong2 s01; s01.x=a0[0]; s01.y=a0[1]; *(ulonglong2*)o0 = s01;
    ulonglong2 s23; s23.x=a0[2]; s23.y=a0[3]; *((ulonglong2*)o0 + 1) = s23;
    float* o1 = o0 + EE;
    ulonglong2 t01; t01.x=a1[0]; t01.y=a1[1]; *(ulonglong2*)o1 = t01;
    ulonglong2 t23; t23.x=a1[2]; t23.y=a1[3]; *((ulonglong2*)o1 + 1) = t23;
}

extern "C" void kernel_launch(void* const* d_in, const int* in_sizes, int n_in,
                              void* d_out, int out_size){
    (void)in_sizes; (void)n_in; (void)out_size;
    const float* x     = (const float*)d_in[0];
    const float* theta = (const float*)d_in[1];
    const float* proj  = (const float*)d_in[2];
    const float* qw    = (const float*)d_in[3];
    const float* qb    = (const float*)d_in[4];
    const float* kw    = (const float*)d_in[5];
    const float* kb    = (const float*)d_in[6];
    const float* vw    = (const float*)d_in[7];
    const float* vb    = (const float*)d_in[8];
    const float* ow    = (const float*)d_in[9];
    const float* ob    = (const float*)d_in[10];
    float* out = (float*)d_out;

    k_qo  <<<(BB*SS*NW + 255)/256, 256>>>(x, theta);
    k_proj<<<(3*EE*32 + 255)/256, 256>>>(qw, kw, vw, proj);
    k_M   <<<HH, 96>>>(qb, kb);
    k_G   <<<EE, 128>>>(ow, vb, ob);
    k_attn<<<dim3(SS/TQ, HH, BB*SPL), 64>>>();
    k_red <<<(BB*SS*HH + 255)/256, 256>>>();
    k_out <<<dim3(BB*SS/64, EE/64), 256>>>(out);
}

// round 7
// speedup vs baseline: 2.5128x; 2.2052x over previous
#include <cuda_runtime.h>
#include <cuda_fp16.h>

#define BB 4
#define SS 2048
#define EE 1024
#define HH 16
#define HD 64
#define NW 8
#define CHK 128          // keys per SMEM chunk
#define KS32 12          // f32 words per key in kf32 tile (conflict-free)
#define KS16 136         // halves per dim row in kf16T tile (conflict-free)

typedef unsigned long long ull;
typedef unsigned int u32;

__device__ __forceinline__ ull fma2(ull a, ull b, ull c){
    ull d; asm("fma.rn.f32x2 %0, %1, %2, %3;" : "=l"(d) : "l"(a), "l"(b), "l"(c)); return d;
}
__device__ __forceinline__ ull add2(ull a, ull b){
    ull d; asm("add.rn.f32x2 %0, %1, %2;" : "=l"(d) : "l"(a), "l"(b)); return d;
}
__device__ __forceinline__ ull pack2(float lo, float hi){
    ull d; asm("mov.b64 %0, {%1, %2};" : "=l"(d) : "f"(lo), "f"(hi)); return d;
}
__device__ __forceinline__ u32 tf32r(float f){
    u32 u; asm("cvt.rna.tf32.f32 %0, %1;" : "=r"(u) : "f"(f)); return u;
}
__device__ __forceinline__ u32 f16x2of(float hi, float lo){
    u32 u; asm("cvt.rn.f16x2.f32 %0, %1, %2;" : "=r"(u) : "f"(hi), "f"(lo)); return u;
}
__device__ __forceinline__ u32 ex2h2(u32 s){
    u32 d; asm("ex2.approx.f16x2 %0, %1;" : "=r"(d) : "r"(s)); return d;
}
__device__ __forceinline__ void mma_tf32(float&c0,float&c1,float&c2,float&c3,
    u32 a0,u32 a1,u32 a2,u32 a3, u32 b0,u32 b1){
    asm("mma.sync.aligned.m16n8k8.row.col.f32.tf32.tf32.f32 "
        "{%0,%1,%2,%3}, {%4,%5,%6,%7}, {%8,%9}, {%10,%11,%12,%13};"
        : "=f"(c0),"=f"(c1),"=f"(c2),"=f"(c3)
        : "r"(a0),"r"(a1),"r"(a2),"r"(a3), "r"(b0),"r"(b1),
          "f"(0.f),"f"(0.f),"f"(0.f),"f"(0.f));
}
__device__ __forceinline__ void mma_f16(float&c0,float&c1,float&c2,float&c3,
    u32 a0,u32 a1,u32 a2,u32 a3, u32 b0,u32 b1){
    asm("mma.sync.aligned.m16n8k16.row.col.f32.f16.f16.f32 "
        "{%0,%1,%2,%3}, {%4,%5,%6,%7}, {%8,%9}, {%0,%1,%2,%3};"
        : "+f"(c0),"+f"(c1),"+f"(c2),"+f"(c3)
        : "r"(a0),"r"(a1),"r"(a2),"r"(a3), "r"(b0),"r"(b1));
}

// Scratch (static device memory — no allocations)
__device__ __align__(16) float g_qo[BB*SS*NW];        // cos(x+theta), plain f32
__device__ __align__(16) float g_qp[EE*NW];
__device__ __align__(16) float g_kp[EE*NW];
__device__ __align__(16) float g_vp[EE*NW];
__device__ __align__(16) float g_M[HH*81];            // per-head 9x9 (log2e/8 folded)
__device__ __align__(16) float g_G[HH*NW*EE];         // [128][1024]
__device__ __align__(16) float g_bias2[EE];           // out_w@v_b + out_b
__device__ __align__(16) float g_Z[BB*SS*HH*NW];      // [8192][128] normalized z

// ---------------- K1: qo = cos(x[..., :8] + theta) ----------------
__global__ void k_qo(const float* __restrict__ x, const float* __restrict__ theta){
    int idx = blockIdx.x*blockDim.x + threadIdx.x;
    if (idx >= BB*SS*NW) return;
    int i = idx & 7;
    int row = idx >> 3;
    g_qo[idx] = cosf(x[(size_t)row*EE + i] + theta[i]);
}

// ---------------- K2: qp/kp/vp[e][i] = sum_k W[e][k] * proj[k][i] ----------------
__global__ void k_proj(const float* __restrict__ qw, const float* __restrict__ kw,
                       const float* __restrict__ vw, const float* __restrict__ proj){
    int gw = (blockIdx.x*blockDim.x + threadIdx.x) >> 5;
    int lane = threadIdx.x & 31;
    if (gw >= 3*EE) return;
    int mat = gw >> 10;
    int e = gw & 1023;
    const float* W = (mat==0) ? qw : (mat==1 ? kw : vw);
    float acc[8];
    #pragma unroll
    for (int i=0;i<8;i++) acc[i]=0.f;
    for (int k=lane; k<EE; k+=32){
        float wv = W[(size_t)e*EE + k];
        float4 p0 = *(const float4*)(proj + k*8);
        float4 p1 = *(const float4*)(proj + k*8 + 4);
        acc[0] += wv*p0.x; acc[1] += wv*p0.y; acc[2] += wv*p0.z; acc[3] += wv*p0.w;
        acc[4] += wv*p1.x; acc[5] += wv*p1.y; acc[6] += wv*p1.z; acc[7] += wv*p1.w;
    }
    #pragma unroll
    for (int off=16; off; off>>=1){
        #pragma unroll
        for (int i=0;i<8;i++) acc[i] += __shfl_down_sync(0xffffffffu, acc[i], off);
    }
    if (lane==0){
        float* dst = (mat==0 ? g_qp : (mat==1 ? g_kp : g_vp)) + e*8;
        *(float4*)dst     = make_float4(acc[0],acc[1],acc[2],acc[3]);
        *(float4*)(dst+4) = make_float4(acc[4],acc[5],acc[6],acc[7]);
    }
}

// ---------------- K3: per-head augmented 9x9 score matrix (log2e/8 folded) ----------------
__global__ void k_M(const float* __restrict__ qb, const float* __restrict__ kb){
    int h = blockIdx.x;
    int t = threadIdx.x;
    if (t >= 81) return;
    int i = t/9, j = t%9;
    float s = 0.f;
    #pragma unroll 8
    for (int d=0; d<HD; d++){
        int r = h*HD + d;
        float a  = (i<8) ? g_qp[r*8+i] : qb[r];
        float bv = (j<8) ? g_kp[r*8+j] : kb[r];
        s += a*bv;
    }
    g_M[h*81+t] = s * 0.125f * 1.4426950408889634f;
}

// ---------------- K4: G[j=h*8+i][e] = sum_d out_w[e][h*64+d]*vp[h*64+d][i]; bias2 ----------------
__global__ void k_G(const float* __restrict__ ow, const float* __restrict__ vb,
                    const float* __restrict__ ob){
    __shared__ __align__(16) float row[EE];
    __shared__ float pb[128];
    int e = blockIdx.x, tid = threadIdx.x;
    const float4* src4 = (const float4*)(ow + (size_t)e*EE);
    float4* row4 = (float4*)row;
    #pragma unroll
    for (int k=tid; k<EE/4; k+=128) row4[k] = src4[k];
    __syncthreads();
    int h = tid >> 3, i = tid & 7;
    float s = 0.f;
    #pragma unroll 8
    for (int d=0; d<HD; d++) s += row[h*HD+d] * g_vp[(h*HD+d)*8 + i];
    g_G[(size_t)tid*EE + e] = s;
    float bacc = 0.f;
    for (int k=tid; k<EE; k+=128) bacc += row[k]*vb[k];
    pb[tid] = bacc; __syncthreads();
    for (int off=64; off; off>>=1){
        if (tid<off) pb[tid] += pb[tid+off];
        __syncthreads();
    }
    if (tid==0) g_bias2[e] = pb[0] + ob[e];
}

// ---------------- K5: tensor-core attention in compressed 8-dim space ----------------
// CTA = 256 thr (8 warps), one (b, h, 128-q block). Each warp: 16 q-rows x all 2048 keys.
// QK: m16n8k8 tf32 (t8 per-row constant dropped — softmax invariant).
// p = ex2.f16x2(score) -> directly the m16n8k16 A fragment for PV (z) and ones-mma (l).
__global__ __launch_bounds__(256) void k_attn(){
    __shared__ __align__(16) float sM[81];
    __shared__ __align__(16) float kf32[CHK*KS32];   // [key][dim] tf32-rounded, stride 12
    __shared__ __align__(16) __half kf16[8*KS16];    // [dim][key] fp16, stride 136
    int tid = threadIdx.x;
    int lane = tid & 31, w = tid >> 5;
    int b = blockIdx.z, h = blockIdx.y;
    int qbase = blockIdx.x*128 + w*16;
    int g = lane >> 2, c = lane & 3;

    if (tid < 81) sM[tid] = g_M[h*81 + tid];
    __syncthreads();

    // A fragment: t[row][col] for rows {g, g+8}, cols {c, c+4} (t8 dropped)
    const float* qA = g_qo + (size_t)(b*SS + qbase + g)*NW;
    const float* qB = qA + 8*NW;
    float qvA[8], qvB[8];
    #pragma unroll
    for (int i=0;i<8;i++){ qvA[i]=qA[i]; qvB[i]=qB[i]; }
    float tA0 = sM[72+c],   tB0 = sM[72+c];
    float tA1 = sM[72+c+4], tB1 = sM[72+c+4];
    #pragma unroll
    for (int i=0;i<8;i++){
        tA0 += qvA[i]*sM[i*9+c];   tB0 += qvB[i]*sM[i*9+c];
        tA1 += qvA[i]*sM[i*9+c+4]; tB1 += qvB[i]*sM[i*9+c+4];
    }
    u32 a0 = tf32r(tA0), a1 = tf32r(tB0), a2 = tf32r(tA1), a3 = tf32r(tB1);

    float zc0=0.f, zc1=0.f, zc2=0.f, zc3=0.f;     // z accumulator (PV mma C)
    float lc0=0.f, lc1=0.f, lc2=0.f, lc3=0.f;     // l accumulator (ones mma C)
    u32 bone = (g==0) ? 0x3C003C00u : 0u;         // ones column in B

    const float* kvsrc = g_qo + (size_t)b*SS*NW;
    for (int ch=0; ch<SS/CHK; ch++){
        __syncthreads();
        #pragma unroll
        for (int r=0; r<2; r++){
            int p = tid + r*256;                  // float2 index in chunk (512 total)
            int key = p >> 2, dp = (p & 3)*2;
            float2 v = *(const float2*)(kvsrc + (size_t)(ch*CHK + key)*NW + dp);
            float2 vr;
            vr.x = __uint_as_float(tf32r(v.x));
            vr.y = __uint_as_float(tf32r(v.y));
            *(float2*)&kf32[key*KS32 + dp] = vr;
            kf16[dp*KS16 + key]     = __float2half(v.x);
            kf16[(dp+1)*KS16 + key] = __float2half(v.y);
        }
        __syncthreads();
        #pragma unroll
        for (int t16=0; t16<CHK/16; t16++){
            int k0 = t16*16;
            // QK B fragments: tile0 keys k0+g, tile1 keys k0+8+g
            u32 b0 = __float_as_uint(kf32[(k0+g)*KS32 + c]);
            u32 b1 = __float_as_uint(kf32[(k0+g)*KS32 + c + 4]);
            u32 b2 = __float_as_uint(kf32[(k0+8+g)*KS32 + c]);
            u32 b3 = __float_as_uint(kf32[(k0+8+g)*KS32 + c + 4]);
            float c0,c1,c2,c3, d0,d1,d2,d3;
            mma_tf32(c0,c1,c2,c3, a0,a1,a2,a3, b0,b1);
            mma_tf32(d0,d1,d2,d3, a0,a1,a2,a3, b2,b3);
            // p = 2^score, packed as PV A fragment (C->A layout identity)
            u32 p0 = ex2h2(f16x2of(c1, c0));
            u32 p1 = ex2h2(f16x2of(c3, c2));
            u32 p2 = ex2h2(f16x2of(d1, d0));
            u32 p3 = ex2h2(f16x2of(d3, d2));
            // PV B: [key][dim] -> kf16T[dim g][keys c*2..], k-rows 0-7 (b) and 8-15
            u32 vb0 = *(const u32*)&kf16[g*KS16 + k0 + c*2];
            u32 vb1 = *(const u32*)&kf16[g*KS16 + k0 + c*2 + 8];
            mma_f16(zc0,zc1,zc2,zc3, p0,p1,p2,p3, vb0,vb1);
            mma_f16(lc0,lc1,lc2,lc3, p0,p1,p2,p3, bone,bone);
        }
    }

    // l lives in col 0 (lanes with c==0); broadcast to the row group
    float la = __shfl_sync(0xffffffffu, lc0, lane & ~3);
    float lb = __shfl_sync(0xffffffffu, lc2, lane & ~3);
    float ia = 1.0f/la, ib = 1.0f/lb;
    int rowA = b*SS + qbase + g;
    float* dA = g_Z + (size_t)rowA*(HH*NW) + h*NW + c*2;
    float* dB = dA + (size_t)8*(HH*NW);
    *(float2*)dA = make_float2(zc0*ia, zc1*ia);
    *(float2*)dB = make_float2(zc2*ib, zc3*ib);
}

// ---------------- K6: out = Z @ G^T + bias2 ----------------
__global__ __launch_bounds__(256) void k_out(float* __restrict__ out){
    __shared__ __align__(16) float Zt[64*66];   // [k][66-pad]: Zt[k][r]
    __shared__ __align__(16) float Gs[64*64];   // [j][c]
    int tid = threadIdx.x;
    int row0 = blockIdx.x*64;
    int col0 = blockIdx.y*64;
    int rp = tid & 31, cg = tid >> 5;

    ull a0[4], a1[4];
    #pragma unroll
    for (int m=0;m<4;m++){ a0[m]=0ull; a1[m]=0ull; }

    for (int kk=0; kk<2; kk++){
        __syncthreads();
        for (int idx=tid; idx<4096; idx+=256){
            int k = idx & 63, r = idx >> 6;
            Zt[k*66 + r] = g_Z[(size_t)(row0+r)*(HH*NW) + kk*64 + k];
        }
        for (int idx=tid; idx<4096; idx+=256){
            int cc = idx & 63, j = idx >> 6;
            Gs[j*64 + cc] = g_G[(size_t)(kk*64+j)*EE + col0 + cc];
        }
        __syncthreads();
        #pragma unroll 16
        for (int k=0; k<64; k++){
            float2 zz = *(const float2*)&Zt[k*66 + rp*2];
            const ulonglong2* g2 = (const ulonglong2*)&Gs[k*64 + cg*8];
            ulonglong2 gA = g2[0], gB = g2[1];
            ull dA = pack2(zz.x, zz.x);
            ull dB = pack2(zz.y, zz.y);
            a0[0]=fma2(dA,gA.x,a0[0]); a0[1]=fma2(dA,gA.y,a0[1]);
            a0[2]=fma2(dA,gB.x,a0[2]); a0[3]=fma2(dA,gB.y,a0[3]);
            a1[0]=fma2(dB,gA.x,a1[0]); a1[1]=fma2(dB,gA.y,a1[1]);
            a1[2]=fma2(dB,gB.x,a1[2]); a1[3]=fma2(dB,gB.y,a1[3]);
        }
    }

    int col = col0 + cg*8;
    const float* bz = g_bias2 + col;
    ull b01 = pack2(bz[0],bz[1]), b23 = pack2(bz[2],bz[3]);
    ull b45 = pack2(bz[4],bz[5]), b67 = pack2(bz[6],bz[7]);
    a0[0]=add2(a0[0],b01); a0[1]=add2(a0[1],b23);
    a0[2]=add2(a0[2],b45); a0[3]=add2(a0[3],b67);
    a1[0]=add2(a1[0],b01); a1[1]=add2(a1[1],b23);
    a1[2]=add2(a1[2],b45); a1[3]=add2(a1[3],b67);

    int r0 = row0 + rp*2;
    float* o0 = out + (size_t)r0*EE + col;
    ulonglong2 s01; s01.x=a0[0]; s01.y=a0[1]; *(ulonglong2*)o0 = s01;
    ulonglong2 s23; s23.x=a0[2]; s23.y=a0[3]; *((ulonglong2*)o0 + 1) = s23;
    float* o1 = o0 + EE;
    ulonglong2 t01; t01.x=a1[0]; t01.y=a1[1]; *(ulonglong2*)o1 = t01;
    ulonglong2 t23; t23.x=a1[2]; t23.y=a1[3]; *((ulonglong2*)o1 + 1) = t23;
}

extern "C" void kernel_launch(void* const* d_in, const int* in_sizes, int n_in,
                              void* d_out, int out_size){
    (void)in_sizes; (void)n_in; (void)out_size;
    const float* x     = (const float*)d_in[0];
    const float* theta = (const float*)d_in[1];
    const float* proj  = (const float*)d_in[2];
    const float* qw    = (const float*)d_in[3];
    const float* qb    = (const float*)d_in[4];
    const float* kw    = (const float*)d_in[5];
    const float* kb    = (const float*)d_in[6];
    const float* vw    = (const float*)d_in[7];
    const float* vb    = (const float*)d_in[8];
    const float* ow    = (const float*)d_in[9];
    const float* ob    = (const float*)d_in[10];
    float* out = (float*)d_out;

    k_qo  <<<(BB*SS*NW + 255)/256, 256>>>(x, theta);
    k_proj<<<(3*EE*32 + 255)/256, 256>>>(qw, kw, vw, proj);
    k_M   <<<HH, 96>>>(qb, kb);
    k_G   <<<EE, 128>>>(ow, vb, ob);
    k_attn<<<dim3(SS/128, HH, BB), 256>>>();
    k_out <<<dim3(BB*SS/64, EE/64), 256>>>(out);
}

// round 10
// speedup vs baseline: 3.3935x; 1.3505x over previous
#include <cuda_runtime.h>
#include <cuda_fp16.h>

#define BB 4
#define SS 2048
#define EE 1024
#define HH 16
#define HD 64
#define NW 8
#define CHK 128          // keys per SMEM chunk in k_attn
#define KS32 12          // f32 words per key in kf32 tile (conflict-free)
#define KS16 136         // halves per dim row in kf16T tile (conflict-free)
#define ZK 128           // K dim of output GEMM
#define OS 136           // smem half-stride for k_out tiles (conflict-free)

typedef unsigned long long ull;
typedef unsigned int u32;
typedef unsigned short u16;

__device__ __forceinline__ u32 tf32r(float f){
    u32 u; asm("cvt.rna.tf32.f32 %0, %1;" : "=r"(u) : "f"(f)); return u;
}
__device__ __forceinline__ u32 f16x2of(float hi, float lo){
    u32 u; asm("cvt.rn.f16x2.f32 %0, %1, %2;" : "=r"(u) : "f"(hi), "f"(lo)); return u;
}
__device__ __forceinline__ u32 ex2h2(u32 s){
    u32 d; asm("ex2.approx.f16x2 %0, %1;" : "=r"(d) : "r"(s)); return d;
}
__device__ __forceinline__ u32 bf16x2of(float hi, float lo){
    u32 d; asm("cvt.rn.bf16x2.f32 %0, %1, %2;" : "=r"(d) : "f"(hi), "f"(lo)); return d;
}
__device__ __forceinline__ float bflo(u32 p){ return __uint_as_float(p << 16); }
__device__ __forceinline__ float bfhi(u32 p){ return __uint_as_float(p & 0xffff0000u); }
__device__ __forceinline__ void mma_tf32(float&c0,float&c1,float&c2,float&c3,
    u32 a0,u32 a1,u32 a2,u32 a3, u32 b0,u32 b1){
    asm("mma.sync.aligned.m16n8k8.row.col.f32.tf32.tf32.f32 "
        "{%0,%1,%2,%3}, {%4,%5,%6,%7}, {%8,%9}, {%10,%11,%12,%13};"
        : "=f"(c0),"=f"(c1),"=f"(c2),"=f"(c3)
        : "r"(a0),"r"(a1),"r"(a2),"r"(a3), "r"(b0),"r"(b1),
          "f"(0.f),"f"(0.f),"f"(0.f),"f"(0.f));
}
__device__ __forceinline__ void mma_f16(float&c0,float&c1,float&c2,float&c3,
    u32 a0,u32 a1,u32 a2,u32 a3, u32 b0,u32 b1){
    asm("mma.sync.aligned.m16n8k16.row.col.f32.f16.f16.f32 "
        "{%0,%1,%2,%3}, {%4,%5,%6,%7}, {%8,%9}, {%0,%1,%2,%3};"
        : "+f"(c0),"+f"(c1),"+f"(c2),"+f"(c3)
        : "r"(a0),"r"(a1),"r"(a2),"r"(a3), "r"(b0),"r"(b1));
}
__device__ __forceinline__ void mma_bf16(float&c0,float&c1,float&c2,float&c3,
    u32 a0,u32 a1,u32 a2,u32 a3, u32 b0,u32 b1){
    asm("mma.sync.aligned.m16n8k16.row.col.f32.bf16.bf16.f32 "
        "{%0,%1,%2,%3}, {%4,%5,%6,%7}, {%8,%9}, {%0,%1,%2,%3};"
        : "+f"(c0),"+f"(c1),"+f"(c2),"+f"(c3)
        : "r"(a0),"r"(a1),"r"(a2),"r"(a3), "r"(b0),"r"(b1));
}

// Scratch (static device memory — no allocations)
__device__ __align__(16) float g_qo[BB*SS*NW];        // cos(x+theta), tf32-pre-rounded f32
__device__ __align__(16) u16   g_kh[BB*NW*SS];        // keys fp16, [b][dim][key]
__device__ __align__(16) float g_qp[EE*NW];
__device__ __align__(16) float g_kp[EE*NW];
__device__ __align__(16) float g_vp[EE*NW];
__device__ __align__(16) float g_M[HH*81];            // per-head 9x9 (log2e/8 folded)
__device__ __align__(16) float g_bias2[EE];           // out_w@v_b + out_b
__device__ __align__(16) u32   g_Zhi[BB*SS*ZK/2];     // z bf16 hi, [row][k] packed pairs
__device__ __align__(16) u32   g_Zlo[BB*SS*ZK/2];     // z bf16 lo
__device__ __align__(16) u16   g_GThi[EE*ZK];         // G^T bf16 hi, [e][k]
__device__ __align__(16) u16   g_GTlo[EE*ZK];         // G^T bf16 lo

// ---------------- K1: qo = tf32(cos(x[..., :8]+theta)); keys fp16 transposed ----------------
__global__ void k_qo(const float* __restrict__ x, const float* __restrict__ theta){
    int idx = blockIdx.x*blockDim.x + threadIdx.x;
    if (idx >= BB*SS*NW) return;
    int i = idx & 7;
    int row = idx >> 3;
    float v = cosf(x[(size_t)row*EE + i] + theta[i]);
    g_qo[idx] = __uint_as_float(tf32r(v));
    int b = row >> 11, key = row & 2047;
    __half hv = __float2half(v);
    g_kh[((size_t)b*NW + i)*SS + key] = *(u16*)&hv;
}

// ---------------- K2: qp/kp/vp[e][i] = sum_k W[e][k] * proj[k][i] ----------------
__global__ void k_proj(const float* __restrict__ qw, const float* __restrict__ kw,
                       const float* __restrict__ vw, const float* __restrict__ proj){
    int gw = (blockIdx.x*blockDim.x + threadIdx.x) >> 5;
    int lane = threadIdx.x & 31;
    if (gw >= 3*EE) return;
    int mat = gw >> 10;
    int e = gw & 1023;
    const float* W = (mat==0) ? qw : (mat==1 ? kw : vw);
    float acc[8];
    #pragma unroll
    for (int i=0;i<8;i++) acc[i]=0.f;
    for (int k=lane; k<EE; k+=32){
        float wv = W[(size_t)e*EE + k];
        float4 p0 = *(const float4*)(proj + k*8);
        float4 p1 = *(const float4*)(proj + k*8 + 4);
        acc[0] += wv*p0.x; acc[1] += wv*p0.y; acc[2] += wv*p0.z; acc[3] += wv*p0.w;
        acc[4] += wv*p1.x; acc[5] += wv*p1.y; acc[6] += wv*p1.z; acc[7] += wv*p1.w;
    }
    #pragma unroll
    for (int off=16; off; off>>=1){
        #pragma unroll
        for (int i=0;i<8;i++) acc[i] += __shfl_down_sync(0xffffffffu, acc[i], off);
    }
    if (lane==0){
        float* dst = (mat==0 ? g_qp : (mat==1 ? g_kp : g_vp)) + e*8;
        *(float4*)dst     = make_float4(acc[0],acc[1],acc[2],acc[3]);
        *(float4*)(dst+4) = make_float4(acc[4],acc[5],acc[6],acc[7]);
    }
}

// ---------------- K3: per-head augmented 9x9 score matrix (log2e/8 folded) ----------------
__global__ void k_M(const float* __restrict__ qb, const float* __restrict__ kb){
    int h = blockIdx.x;
    int t = threadIdx.x;
    if (t >= 81) return;
    int i = t/9, j = t%9;
    float s = 0.f;
    #pragma unroll 8
    for (int d=0; d<HD; d++){
        int r = h*HD + d;
        float a  = (i<8) ? g_qp[r*8+i] : qb[r];
        float bv = (j<8) ? g_kp[r*8+j] : kb[r];
        s += a*bv;
    }
    g_M[h*81+t] = s * 0.125f * 1.4426950408889634f;
}

// ---------------- K4: GT[e][j=h*8+i] = sum_d ow[e][h*64+d]*vp[h*64+d][i] (bf16 split); bias2 ----------------
// R7-proven body + bf16 hi/lo split output + shuffle bias reduction.
__global__ __launch_bounds__(128) void k_G(const float* __restrict__ ow, const float* __restrict__ vb,
                    const float* __restrict__ ob){
    __shared__ __align__(16) float row[EE];
    __shared__ float pr[4];
    int e = blockIdx.x, tid = threadIdx.x;
    const float4* src4 = (const float4*)(ow + (size_t)e*EE);
    float4* row4 = (float4*)row;
    #pragma unroll
    for (int k=tid; k<EE/4; k+=128) row4[k] = src4[k];
    __syncthreads();
    int h = tid >> 3, i = tid & 7;
    float s = 0.f;
    #pragma unroll 8
    for (int d=0; d<HD; d++) s += row[h*HD+d] * g_vp[(h*HD+d)*8 + i];

    // bf16 split write to GT[e][tid]
    u32 p = bf16x2of(0.f, s);
    float shi = bflo(p);
    u32 pl = bf16x2of(0.f, s - shi);
    g_GThi[(size_t)e*ZK + tid] = (u16)(p & 0xffffu);
    g_GTlo[(size_t)e*ZK + tid] = (u16)(pl & 0xffffu);

    // bias2: warp-level reduce, 4 partials
    float bacc = 0.f;
    #pragma unroll
    for (int k=tid; k<EE; k+=128) bacc += row[k]*vb[k];
    #pragma unroll
    for (int off=16; off; off>>=1) bacc += __shfl_down_sync(0xffffffffu, bacc, off);
    if ((tid & 31)==0) pr[tid>>5] = bacc;
    __syncthreads();
    if (tid==0) g_bias2[e] = pr[0]+pr[1]+pr[2]+pr[3] + ob[e];
}

// ---------------- K5: tensor-core attention in compressed 8-dim space ----------------
__global__ __launch_bounds__(256) void k_attn(){
    __shared__ __align__(16) float sM[81];
    __shared__ __align__(16) float kf32[CHK*KS32];   // [key][dim] tf32 values, stride 12
    __shared__ __align__(16) __half kf16[8*KS16];    // [dim][key] fp16, stride 136
    int tid = threadIdx.x;
    int lane = tid & 31, w = tid >> 5;
    int b = blockIdx.z, h = blockIdx.y;
    int qbase = blockIdx.x*128 + w*16;
    int g = lane >> 2, c = lane & 3;

    if (tid < 81) sM[tid] = g_M[h*81 + tid];
    __syncthreads();

    // A fragment: t[row][col] for rows {g, g+8}, cols {c, c+4} (t8 constant dropped)
    const float* qA = g_qo + (size_t)(b*SS + qbase + g)*NW;
    const float* qB = qA + 8*NW;
    float qvA[8], qvB[8];
    #pragma unroll
    for (int i=0;i<8;i++){ qvA[i]=qA[i]; qvB[i]=qB[i]; }
    float tA0 = sM[72+c],   tB0 = sM[72+c];
    float tA1 = sM[72+c+4], tB1 = sM[72+c+4];
    #pragma unroll
    for (int i=0;i<8;i++){
        tA0 += qvA[i]*sM[i*9+c];   tB0 += qvB[i]*sM[i*9+c];
        tA1 += qvA[i]*sM[i*9+c+4]; tB1 += qvB[i]*sM[i*9+c+4];
    }
    u32 a0 = tf32r(tA0), a1 = tf32r(tB0), a2 = tf32r(tA1), a3 = tf32r(tB1);

    float zc0=0.f, zc1=0.f, zc2=0.f, zc3=0.f;
    float lc0=0.f, lc1=0.f, lc2=0.f, lc3=0.f;
    u32 bone = (g==0) ? 0x3C003C00u : 0u;

    const float4* ksrc = (const float4*)(g_qo + (size_t)b*SS*NW);
    const uint4* hsrc = (const uint4*)(g_kh + (size_t)b*NW*SS);
    for (int ch=0; ch<SS/CHK; ch++){
        __syncthreads();
        {   // kf32: 128 keys x 8 f32 (already tf32-rounded)
            int key = tid >> 1, hf = tid & 1;
            float4 f4 = ksrc[ch*256 + tid];
            *(float4*)&kf32[key*KS32 + hf*4] = f4;
            // kf16: 8 dims x 128 keys, from pre-transposed g_kh
            if (tid < 128){
                int dim = tid >> 4, seg = tid & 15;
                uint4 h4 = hsrc[(dim*SS + ch*CHK)/8 + seg];
                *(uint4*)&kf16[dim*KS16 + seg*8] = h4;
            }
        }
        __syncthreads();
        #pragma unroll
        for (int t16=0; t16<CHK/16; t16++){
            int k0 = t16*16;
            u32 b0 = __float_as_uint(kf32[(k0+g)*KS32 + c]);
            u32 b1 = __float_as_uint(kf32[(k0+g)*KS32 + c + 4]);
            u32 b2 = __float_as_uint(kf32[(k0+8+g)*KS32 + c]);
            u32 b3 = __float_as_uint(kf32[(k0+8+g)*KS32 + c + 4]);
            float c0,c1,c2,c3, d0,d1,d2,d3;
            mma_tf32(c0,c1,c2,c3, a0,a1,a2,a3, b0,b1);
            mma_tf32(d0,d1,d2,d3, a0,a1,a2,a3, b2,b3);
            u32 p0 = ex2h2(f16x2of(c1, c0));
            u32 p1 = ex2h2(f16x2of(c3, c2));
            u32 p2 = ex2h2(f16x2of(d1, d0));
            u32 p3 = ex2h2(f16x2of(d3, d2));
            u32 vb0 = *(const u32*)&kf16[g*KS16 + k0 + c*2];
            u32 vb1 = *(const u32*)&kf16[g*KS16 + k0 + c*2 + 8];
            mma_f16(zc0,zc1,zc2,zc3, p0,p1,p2,p3, vb0,vb1);
            mma_f16(lc0,lc1,lc2,lc3, p0,p1,p2,p3, bone,bone);
        }
    }

    float la = __shfl_sync(0xffffffffu, lc0, lane & ~3);
    float lb = __shfl_sync(0xffffffffu, lc2, lane & ~3);
    float ia = 1.0f/la, ib = 1.0f/lb;
    float z0 = zc0*ia, z1 = zc1*ia, z2 = zc2*ib, z3 = zc3*ib;

    // bf16 hi/lo split writes: g_Z*[row][k] with k = h*8 + c*2 (.x), +1 (.y)
    int rowA = b*SS + qbase + g;
    size_t iA = (size_t)rowA*(ZK/2) + h*4 + c;
    size_t iB = iA + 8*(ZK/2);
    u32 hA = bf16x2of(z1, z0);
    u32 lA = bf16x2of(z1 - bfhi(hA), z0 - bflo(hA));
    u32 hB = bf16x2of(z3, z2);
    u32 lB = bf16x2of(z3 - bfhi(hB), z2 - bflo(hB));
    g_Zhi[iA] = hA; g_Zlo[iA] = lA;
    g_Zhi[iB] = hB; g_Zlo[iB] = lB;
}

// ---------------- K6: out = Z @ G^T + bias2, bf16-split tensor-core GEMM ----------------
// CTA: 128 rows x 128 cols, full K=128 in smem. 8 warps, each 16 rows x 128 cols.
__global__ __launch_bounds__(256) void k_out(float* __restrict__ out){
    extern __shared__ __align__(16) char smem[];
    __half* sZh = (__half*)smem;                 // [128][OS]
    __half* sZl = sZh + 128*OS;
    __half* sGh = sZl + 128*OS;                  // [e 128][OS]
    __half* sGl = sGh + 128*OS;
    float*  sB  = (float*)(sGl + 128*OS);        // 128 bias values

    int tid = threadIdx.x;
    int lane = tid & 31, w = tid >> 5;
    int g = lane >> 2, c = lane & 3;
    int rbase = blockIdx.x*128;
    int ebase = blockIdx.y*128;

    const uint4* zh4 = (const uint4*)g_Zhi;
    const uint4* zl4 = (const uint4*)g_Zlo;
    const uint4* gh4 = (const uint4*)g_GThi;
    const uint4* gl4 = (const uint4*)g_GTlo;
    #pragma unroll
    for (int q=tid; q<2048; q+=256){
        int r = q >> 4, seg = q & 15;
        *(uint4*)&sZh[r*OS + seg*8] = zh4[((size_t)(rbase+r)*ZK)/8 + seg];
        *(uint4*)&sZl[r*OS + seg*8] = zl4[((size_t)(rbase+r)*ZK)/8 + seg];
        *(uint4*)&sGh[r*OS + seg*8] = gh4[((size_t)(ebase+r)*ZK)/8 + seg];
        *(uint4*)&sGl[r*OS + seg*8] = gl4[((size_t)(ebase+r)*ZK)/8 + seg];
    }
    if (tid < 128) sB[tid] = g_bias2[ebase + tid];
    __syncthreads();

    float acc[16][4];
    #pragma unroll
    for (int nt=0;nt<16;nt++){ acc[nt][0]=0.f; acc[nt][1]=0.f; acc[nt][2]=0.f; acc[nt][3]=0.f; }

    int rA = w*16 + g;
    #pragma unroll
    for (int ks=0; ks<8; ks++){
        int kb = ks*16 + c*2;
        u32 ah0 = *(const u32*)&sZh[rA*OS + kb];
        u32 ah1 = *(const u32*)&sZh[(rA+8)*OS + kb];
        u32 ah2 = *(const u32*)&sZh[rA*OS + kb + 8];
        u32 ah3 = *(const u32*)&sZh[(rA+8)*OS + kb + 8];
        u32 al0 = *(const u32*)&sZl[rA*OS + kb];
        u32 al1 = *(const u32*)&sZl[(rA+8)*OS + kb];
        u32 al2 = *(const u32*)&sZl[rA*OS + kb + 8];
        u32 al3 = *(const u32*)&sZl[(rA+8)*OS + kb + 8];
        #pragma unroll
        for (int nt=0; nt<16; nt++){
            int eg = nt*8 + g;
            u32 bh0 = *(const u32*)&sGh[eg*OS + kb];
            u32 bh1 = *(const u32*)&sGh[eg*OS + kb + 8];
            u32 bl0 = *(const u32*)&sGl[eg*OS + kb];
            u32 bl1 = *(const u32*)&sGl[eg*OS + kb + 8];
            mma_bf16(acc[nt][0],acc[nt][1],acc[nt][2],acc[nt][3], ah0,ah1,ah2,ah3, bh0,bh1);
            mma_bf16(acc[nt][0],acc[nt][1],acc[nt][2],acc[nt][3], ah0,ah1,ah2,ah3, bl0,bl1);
            mma_bf16(acc[nt][0],acc[nt][1],acc[nt][2],acc[nt][3], al0,al1,al2,al3, bh0,bh1);
        }
    }

    int row0 = rbase + w*16 + g;
    #pragma unroll
    for (int nt=0; nt<16; nt++){
        int col = nt*8 + c*2;
        float b0v = sB[col], b1v = sB[col+1];
        float* o0 = out + (size_t)row0*EE + ebase + col;
        *(float2*)o0 = make_float2(acc[nt][0]+b0v, acc[nt][1]+b1v);
        float* o1 = o0 + (size_t)8*EE;
        *(float2*)o1 = make_float2(acc[nt][2]+b0v, acc[nt][3]+b1v);
    }
}

extern "C" void kernel_launch(void* const* d_in, const int* in_sizes, int n_in,
                              void* d_out, int out_size){
    (void)in_sizes; (void)n_in; (void)out_size;
    const float* x     = (const float*)d_in[0];
    const float* theta = (const float*)d_in[1];
    const float* proj  = (const float*)d_in[2];
    const float* qw    = (const float*)d_in[3];
    const float* qb    = (const float*)d_in[4];
    const float* kw    = (const float*)d_in[5];
    const float* kb    = (const float*)d_in[6];
    const float* vw    = (const float*)d_in[7];
    const float* vb    = (const float*)d_in[8];
    const float* ow    = (const float*)d_in[9];
    const float* ob    = (const float*)d_in[10];
    float* out = (float*)d_out;

    const int OUT_SMEM = 4*128*OS*2 + 128*4;   // 139,776 B
    cudaFuncSetAttribute(k_out, cudaFuncAttributeMaxDynamicSharedMemorySize, OUT_SMEM);

    k_qo  <<<(BB*SS*NW + 255)/256, 256>>>(x, theta);
    k_proj<<<(3*EE*32 + 255)/256, 256>>>(qw, kw, vw, proj);
    k_M   <<<HH, 96>>>(qb, kb);
    k_G   <<<EE, 128>>>(ow, vb, ob);
    k_attn<<<dim3(SS/128, HH, BB), 256>>>();
    k_out <<<dim3(BB*SS/128, EE/128), 256, OUT_SMEM>>>(out);
}

// round 11
// speedup vs baseline: 3.5699x; 1.0520x over previous
#include <cuda_runtime.h>
#include <cuda_fp16.h>

#define BB 4
#define SS 2048
#define EE 1024
#define HH 16
#define HD 64
#define NW 8
#define CHK 128          // keys per SMEM chunk in k_attn
#define KS32 12          // f32 words per key in kf32 tile (conflict-free)
#define KS16 136         // halves per dim row in kf16T tile (conflict-free)
#define ZK 128           // K dim of output GEMM
#define OS 136           // smem half-stride for k_out tiles (conflict-free)
#define GROW 1088        // skewed row stride (words) in k_G: [h*68+d]

typedef unsigned long long ull;
typedef unsigned int u32;
typedef unsigned short u16;

__device__ __forceinline__ u32 tf32r(float f){
    u32 u; asm("cvt.rna.tf32.f32 %0, %1;" : "=r"(u) : "f"(f)); return u;
}
__device__ __forceinline__ u32 f16x2of(float hi, float lo){
    u32 u; asm("cvt.rn.f16x2.f32 %0, %1, %2;" : "=r"(u) : "f"(hi), "f"(lo)); return u;
}
__device__ __forceinline__ u32 ex2h2(u32 s){
    u32 d; asm("ex2.approx.f16x2 %0, %1;" : "=r"(d) : "r"(s)); return d;
}
__device__ __forceinline__ u32 bf16x2of(float hi, float lo){
    u32 d; asm("cvt.rn.bf16x2.f32 %0, %1, %2;" : "=r"(d) : "f"(hi), "f"(lo)); return d;
}
__device__ __forceinline__ float bflo(u32 p){ return __uint_as_float(p << 16); }
__device__ __forceinline__ float bfhi(u32 p){ return __uint_as_float(p & 0xffff0000u); }
__device__ __forceinline__ void cpa16(void* s, const void* g){
    asm volatile("cp.async.ca.shared.global [%0], [%1], 16;"
        :: "r"((u32)__cvta_generic_to_shared(s)), "l"(g));
}
__device__ __forceinline__ void cpa_commit(){ asm volatile("cp.async.commit_group;"); }
template<int N> __device__ __forceinline__ void cpa_wait(){
    asm volatile("cp.async.wait_group %0;" :: "n"(N));
}
__device__ __forceinline__ void mma_tf32(float&c0,float&c1,float&c2,float&c3,
    u32 a0,u32 a1,u32 a2,u32 a3, u32 b0,u32 b1){
    asm("mma.sync.aligned.m16n8k8.row.col.f32.tf32.tf32.f32 "
        "{%0,%1,%2,%3}, {%4,%5,%6,%7}, {%8,%9}, {%10,%11,%12,%13};"
        : "=f"(c0),"=f"(c1),"=f"(c2),"=f"(c3)
        : "r"(a0),"r"(a1),"r"(a2),"r"(a3), "r"(b0),"r"(b1),
          "f"(0.f),"f"(0.f),"f"(0.f),"f"(0.f));
}
__device__ __forceinline__ void mma_f16(float&c0,float&c1,float&c2,float&c3,
    u32 a0,u32 a1,u32 a2,u32 a3, u32 b0,u32 b1){
    asm("mma.sync.aligned.m16n8k16.row.col.f32.f16.f16.f32 "
        "{%0,%1,%2,%3}, {%4,%5,%6,%7}, {%8,%9}, {%0,%1,%2,%3};"
        : "+f"(c0),"+f"(c1),"+f"(c2),"+f"(c3)
        : "r"(a0),"r"(a1),"r"(a2),"r"(a3), "r"(b0),"r"(b1));
}
__device__ __forceinline__ void mma_bf16(float&c0,float&c1,float&c2,float&c3,
    u32 a0,u32 a1,u32 a2,u32 a3, u32 b0,u32 b1){
    asm("mma.sync.aligned.m16n8k16.row.col.f32.bf16.bf16.f32 "
        "{%0,%1,%2,%3}, {%4,%5,%6,%7}, {%8,%9}, {%0,%1,%2,%3};"
        : "+f"(c0),"+f"(c1),"+f"(c2),"+f"(c3)
        : "r"(a0),"r"(a1),"r"(a2),"r"(a3), "r"(b0),"r"(b1));
}

// Scratch (static device memory — no allocations)
__device__ __align__(16) float g_qo[BB*SS*NW];        // cos(x+theta), tf32-pre-rounded f32
__device__ __align__(16) u16   g_kh[BB*NW*SS];        // keys fp16, [b][dim][key]
__device__ __align__(16) float g_qp[EE*NW];
__device__ __align__(16) float g_kp[EE*NW];
__device__ __align__(16) float g_vp[EE*NW];
__device__ __align__(16) float g_M[HH*81];            // per-head 9x9 (log2e/8 folded)
__device__ __align__(16) float g_bias2[EE];           // out_w@v_b + out_b
__device__ __align__(16) u32   g_Zhi[BB*SS*ZK/2];     // z bf16 hi, [row][k] packed pairs
__device__ __align__(16) u32   g_Zlo[BB*SS*ZK/2];     // z bf16 lo
__device__ __align__(16) u16   g_GThi[EE*ZK];         // G^T bf16 hi, [e][k]
__device__ __align__(16) u16   g_GTlo[EE*ZK];         // G^T bf16 lo

// ---------------- K1: qo = tf32(cos(x[..., :8]+theta)); keys fp16 transposed ----------------
__global__ void k_qo(const float* __restrict__ x, const float* __restrict__ theta){
    int idx = blockIdx.x*blockDim.x + threadIdx.x;
    if (idx >= BB*SS*NW) return;
    int i = idx & 7;
    int row = idx >> 3;
    float v = cosf(x[(size_t)row*EE + i] + theta[i]);
    g_qo[idx] = __uint_as_float(tf32r(v));
    int b = row >> 11, key = row & 2047;
    __half hv = __float2half(v);
    g_kh[((size_t)b*NW + i)*SS + key] = *(u16*)&hv;
}

// ---------------- K2: qp/kp/vp[e][i] = sum_k W[e][k] * proj[k][i] ----------------
__global__ void k_proj(const float* __restrict__ qw, const float* __restrict__ kw,
                       const float* __restrict__ vw, const float* __restrict__ proj){
    int gw = (blockIdx.x*blockDim.x + threadIdx.x) >> 5;
    int lane = threadIdx.x & 31;
    if (gw >= 3*EE) return;
    int mat = gw >> 10;
    int e = gw & 1023;
    const float* W = (mat==0) ? qw : (mat==1 ? kw : vw);
    float acc[8];
    #pragma unroll
    for (int i=0;i<8;i++) acc[i]=0.f;
    for (int k=lane; k<EE; k+=32){
        float wv = W[(size_t)e*EE + k];
        float4 p0 = *(const float4*)(proj + k*8);
        float4 p1 = *(const float4*)(proj + k*8 + 4);
        acc[0] += wv*p0.x; acc[1] += wv*p0.y; acc[2] += wv*p0.z; acc[3] += wv*p0.w;
        acc[4] += wv*p1.x; acc[5] += wv*p1.y; acc[6] += wv*p1.z; acc[7] += wv*p1.w;
    }
    #pragma unroll
    for (int off=16; off; off>>=1){
        #pragma unroll
        for (int i=0;i<8;i++) acc[i] += __shfl_down_sync(0xffffffffu, acc[i], off);
    }
    if (lane==0){
        float* dst = (mat==0 ? g_qp : (mat==1 ? g_kp : g_vp)) + e*8;
        *(float4*)dst     = make_float4(acc[0],acc[1],acc[2],acc[3]);
        *(float4*)(dst+4) = make_float4(acc[4],acc[5],acc[6],acc[7]);
    }
}

// ---------------- K3: per-head augmented 9x9 score matrix (log2e/8 folded) ----------------
__global__ void k_M(const float* __restrict__ qb, const float* __restrict__ kb){
    int h = blockIdx.x;
    int t = threadIdx.x;
    if (t >= 81) return;
    int i = t/9, j = t%9;
    float s = 0.f;
    #pragma unroll 8
    for (int d=0; d<HD; d++){
        int r = h*HD + d;
        float a  = (i<8) ? g_qp[r*8+i] : qb[r];
        float bv = (j<8) ? g_kp[r*8+j] : kb[r];
        s += a*bv;
    }
    g_M[h*81+t] = s * 0.125f * 1.4426950408889634f;
}

// ---------------- K4 v3: 4 e-rows per CTA, skewed smem, big MLP ----------------
// GT[e][j=h*8+i] = sum_d ow[e][h*64+d]*vp[h*64+d][i] (bf16 split); bias2.
__global__ __launch_bounds__(256) void k_G(const float* __restrict__ ow, const float* __restrict__ vb,
                    const float* __restrict__ ob){
    __shared__ __align__(16) float rows[4*GROW];   // skewed: word = r*GROW + h*68 + d
    __shared__ float pr[16];
    int tid = threadIdx.x;
    int e0 = blockIdx.x*4;

    // cooperative load: 4 rows x 1024 f32 = 1024 float4, skew +4h words
    const float4* src = (const float4*)(ow + (size_t)e0*EE);
    #pragma unroll
    for (int q=tid; q<1024; q+=256){
        int r = q >> 8;
        int k = (q & 255)*4;
        int h = k >> 6;
        *(float4*)&rows[r*GROW + k + h*4] = src[q];
    }
    __syncthreads();

    // thread (sub = tid>>7, j = tid&127) computes rows {sub, sub+2}
    int sub = tid >> 7, j = tid & 127;
    int h = j >> 3, i = j & 7;
    const float* r0 = rows + sub*GROW + h*68;
    const float* r2 = r0 + 2*GROW;
    float s0 = 0.f, s1 = 0.f;
    #pragma unroll 8
    for (int d=0; d<HD; d++){
        float v = g_vp[(h*HD + d)*NW + i];
        s0 = fmaf(r0[d], v, s0);
        s1 = fmaf(r2[d], v, s1);
    }
    // bf16 hi/lo split writes
    u32 p0 = bf16x2of(0.f, s0); float h0v = bflo(p0); u32 q0 = bf16x2of(0.f, s0 - h0v);
    u32 p1 = bf16x2of(0.f, s1); float h1v = bflo(p1); u32 q1 = bf16x2of(0.f, s1 - h1v);
    g_GThi[(size_t)(e0+sub)*ZK + j]   = (u16)(p0 & 0xffffu);
    g_GTlo[(size_t)(e0+sub)*ZK + j]   = (u16)(q0 & 0xffffu);
    g_GThi[(size_t)(e0+sub+2)*ZK + j] = (u16)(p1 & 0xffffu);
    g_GTlo[(size_t)(e0+sub+2)*ZK + j] = (u16)(q1 & 0xffffu);

    // bias2 for the 4 rows: thread accumulates rows {sub, sub+2}
    float b0 = 0.f, b1 = 0.f;
    #pragma unroll 8
    for (int k=j; k<EE; k+=128){
        int sk = k + ((k >> 6) << 2);
        float vv = vb[k];
        b0 += rows[sub*GROW + sk]*vv;
        b1 += rows[(sub+2)*GROW + sk]*vv;
    }
    #pragma unroll
    for (int off=16; off; off>>=1){
        b0 += __shfl_down_sync(0xffffffffu, b0, off);
        b1 += __shfl_down_sync(0xffffffffu, b1, off);
    }
    if ((tid & 31)==0){
        int w = tid >> 5;                 // warps 0-3: rows 0(b0),2(b1); warps 4-7: rows 1(b0),3(b1)
        pr[w*2]   = b0;
        pr[w*2+1] = b1;
    }
    __syncthreads();
    if (tid < 4){
        int base = (tid & 1)*8;           // rows 1,3 -> warps 4-7
        int off  = (tid >> 1) & 1;        // rows 2,3 -> the b1 slot
        float s = pr[base+off] + pr[base+off+2] + pr[base+off+4] + pr[base+off+6];
        g_bias2[e0 + tid] = s + ob[e0 + tid];
    }
}

// ---------------- K5: tensor-core attention, cp.async double-buffered keys ----------------
__global__ __launch_bounds__(256) void k_attn(){
    __shared__ __align__(16) float sM[81];
    __shared__ __align__(16) float kf32[2][CHK*KS32];   // [key][dim] tf32 values, stride 12
    __shared__ __align__(16) __half kf16[2][8*KS16];    // [dim][key] fp16, stride 136
    int tid = threadIdx.x;
    int lane = tid & 31, w = tid >> 5;
    int b = blockIdx.z, h = blockIdx.y;
    int qbase = blockIdx.x*128 + w*16;
    int g = lane >> 2, c = lane & 3;

    if (tid < 81) sM[tid] = g_M[h*81 + tid];

    const float4* ksrc = (const float4*)(g_qo + (size_t)b*SS*NW);
    const uint4* hsrc = (const uint4*)(g_kh + (size_t)b*NW*SS);

    #define ISSUE(ch, bf) do{ \
        cpa16(&kf32[bf][(tid>>1)*KS32 + (tid&1)*4], ksrc + (ch)*256 + tid); \
        if (tid < 128){ int dim = tid>>4, seg = tid&15; \
            cpa16(&kf16[bf][dim*KS16 + seg*8], hsrc + (dim*SS + (ch)*CHK)/8 + seg); } \
        cpa_commit(); }while(0)

    ISSUE(0, 0);
    ISSUE(1, 1);
    __syncthreads();   // sM ready

    // A fragment: t[row][col] for rows {g, g+8}, cols {c, c+4} (t8 constant dropped)
    const float* qA = g_qo + (size_t)(b*SS + qbase + g)*NW;
    const float* qB = qA + 8*NW;
    float qvA[8], qvB[8];
    #pragma unroll
    for (int i=0;i<8;i++){ qvA[i]=qA[i]; qvB[i]=qB[i]; }
    float tA0 = sM[72+c],   tB0 = sM[72+c];
    float tA1 = sM[72+c+4], tB1 = sM[72+c+4];
    #pragma unroll
    for (int i=0;i<8;i++){
        tA0 += qvA[i]*sM[i*9+c];   tB0 += qvB[i]*sM[i*9+c];
        tA1 += qvA[i]*sM[i*9+c+4]; tB1 += qvB[i]*sM[i*9+c+4];
    }
    u32 a0 = tf32r(tA0), a1 = tf32r(tB0), a2 = tf32r(tA1), a3 = tf32r(tB1);

    float zc0=0.f, zc1=0.f, zc2=0.f, zc3=0.f;
    float lc0=0.f, lc1=0.f, lc2=0.f, lc3=0.f;
    u32 bone = (g==0) ? 0x3C003C00u : 0u;

    #pragma unroll 1
    for (int ch=0; ch<SS/CHK; ch++){
        if (ch < SS/CHK - 2) cpa_wait<1>(); else cpa_wait<0>();
        __syncthreads();
        int bf = ch & 1;
        const float*  kw32 = kf32[bf];
        const __half* kw16 = kf16[bf];
        #pragma unroll
        for (int t16=0; t16<CHK/16; t16++){
            int k0 = t16*16;
            u32 b0 = __float_as_uint(kw32[(k0+g)*KS32 + c]);
            u32 b1 = __float_as_uint(kw32[(k0+g)*KS32 + c + 4]);
            u32 b2 = __float_as_uint(kw32[(k0+8+g)*KS32 + c]);
            u32 b3 = __float_as_uint(kw32[(k0+8+g)*KS32 + c + 4]);
            float c0,c1,c2,c3, d0,d1,d2,d3;
            mma_tf32(c0,c1,c2,c3, a0,a1,a2,a3, b0,b1);
            mma_tf32(d0,d1,d2,d3, a0,a1,a2,a3, b2,b3);
            u32 p0 = ex2h2(f16x2of(c1, c0));
            u32 p1 = ex2h2(f16x2of(c3, c2));
            u32 p2 = ex2h2(f16x2of(d1, d0));
            u32 p3 = ex2h2(f16x2of(d3, d2));
            u32 vb0 = *(const u32*)&kw16[g*KS16 + k0 + c*2];
            u32 vb1 = *(const u32*)&kw16[g*KS16 + k0 + c*2 + 8];
            mma_f16(zc0,zc1,zc2,zc3, p0,p1,p2,p3, vb0,vb1);
            mma_f16(lc0,lc1,lc2,lc3, p0,p1,p2,p3, bone,bone);
        }
        __syncthreads();
        if (ch + 2 < SS/CHK) ISSUE(ch+2, bf);
    }
    #undef ISSUE

    float la = __shfl_sync(0xffffffffu, lc0, lane & ~3);
    float lb = __shfl_sync(0xffffffffu, lc2, lane & ~3);
    float ia = 1.0f/la, ib = 1.0f/lb;
    float z0 = zc0*ia, z1 = zc1*ia, z2 = zc2*ib, z3 = zc3*ib;

    // bf16 hi/lo split writes: g_Z*[row][k] with k = h*8 + c*2 (.x), +1 (.y)
    int rowA = b*SS + qbase + g;
    size_t iA = (size_t)rowA*(ZK/2) + h*4 + c;
    size_t iB = iA + 8*(ZK/2);
    u32 hA = bf16x2of(z1, z0);
    u32 lA = bf16x2of(z1 - bfhi(hA), z0 - bflo(hA));
    u32 hB = bf16x2of(z3, z2);
    u32 lB = bf16x2of(z3 - bfhi(hB), z2 - bflo(hB));
    g_Zhi[iA] = hA; g_Zlo[iA] = lA;
    g_Zhi[iB] = hB; g_Zlo[iB] = lB;
}

// ---------------- K6: out = Z @ G^T + bias2, bf16-split tensor-core GEMM ----------------
__global__ __launch_bounds__(256) void k_out(float* __restrict__ out){
    extern __shared__ __align__(16) char smem[];
    __half* sZh = (__half*)smem;                 // [128][OS]
    __half* sZl = sZh + 128*OS;
    __half* sGh = sZl + 128*OS;                  // [e 128][OS]
    __half* sGl = sGh + 128*OS;
    float*  sB  = (float*)(sGl + 128*OS);        // 128 bias values

    int tid = threadIdx.x;
    int lane = tid & 31, w = tid >> 5;
    int g = lane >> 2, c = lane & 3;
    int rbase = blockIdx.x*128;
    int ebase = blockIdx.y*128;

    const uint4* zh4 = (const uint4*)g_Zhi;
    const uint4* zl4 = (const uint4*)g_Zlo;
    const uint4* gh4 = (const uint4*)g_GThi;
    const uint4* gl4 = (const uint4*)g_GTlo;
    #pragma unroll
    for (int q=tid; q<2048; q+=256){
        int r = q >> 4, seg = q & 15;
        *(uint4*)&sZh[r*OS + seg*8] = zh4[((size_t)(rbase+r)*ZK)/8 + seg];
        *(uint4*)&sZl[r*OS + seg*8] = zl4[((size_t)(rbase+r)*ZK)/8 + seg];
        *(uint4*)&sGh[r*OS + seg*8] = gh4[((size_t)(ebase+r)*ZK)/8 + seg];
        *(uint4*)&sGl[r*OS + seg*8] = gl4[((size_t)(ebase+r)*ZK)/8 + seg];
    }
    if (tid < 128) sB[tid] = g_bias2[ebase + tid];
    __syncthreads();

    float acc[16][4];
    #pragma unroll
    for (int nt=0;nt<16;nt++){ acc[nt][0]=0.f; acc[nt][1]=0.f; acc[nt][2]=0.f; acc[nt][3]=0.f; }

    int rA = w*16 + g;
    #pragma unroll
    for (int ks=0; ks<8; ks++){
        int kb = ks*16 + c*2;
        u32 ah0 = *(const u32*)&sZh[rA*OS + kb];
        u32 ah1 = *(const u32*)&sZh[(rA+8)*OS + kb];
        u32 ah2 = *(const u32*)&sZh[rA*OS + kb + 8];
        u32 ah3 = *(const u32*)&sZh[(rA+8)*OS + kb + 8];
        u32 al0 = *(const u32*)&sZl[rA*OS + kb];
        u32 al1 = *(const u32*)&sZl[(rA+8)*OS + kb];
        u32 al2 = *(const u32*)&sZl[rA*OS + kb + 8];
        u32 al3 = *(const u32*)&sZl[(rA+8)*OS + kb + 8];
        #pragma unroll
        for (int nt=0; nt<16; nt++){
            int eg = nt*8 + g;
            u32 bh0 = *(const u32*)&sGh[eg*OS + kb];
            u32 bh1 = *(const u32*)&sGh[eg*OS + kb + 8];
            u32 bl0 = *(const u32*)&sGl[eg*OS + kb];
            u32 bl1 = *(const u32*)&sGl[eg*OS + kb + 8];
            mma_bf16(acc[nt][0],acc[nt][1],acc[nt][2],acc[nt][3], ah0,ah1,ah2,ah3, bh0,bh1);
            mma_bf16(acc[nt][0],acc[nt][1],acc[nt][2],acc[nt][3], ah0,ah1,ah2,ah3, bl0,bl1);
            mma_bf16(acc[nt][0],acc[nt][1],acc[nt][2],acc[nt][3], al0,al1,al2,al3, bh0,bh1);
        }
    }

    int row0 = rbase + w*16 + g;
    #pragma unroll
    for (int nt=0; nt<16; nt++){
        int col = nt*8 + c*2;
        float b0v = sB[col], b1v = sB[col+1];
        float* o0 = out + (size_t)row0*EE + ebase + col;
        *(float2*)o0 = make_float2(acc[nt][0]+b0v, acc[nt][1]+b1v);
        float* o1 = o0 + (size_t)8*EE;
        *(float2*)o1 = make_float2(acc[nt][2]+b0v, acc[nt][3]+b1v);
    }
}

extern "C" void kernel_launch(void* const* d_in, const int* in_sizes, int n_in,
                              void* d_out, int out_size){
    (void)in_sizes; (void)n_in; (void)out_size;
    const float* x     = (const float*)d_in[0];
    const float* theta = (const float*)d_in[1];
    const float* proj  = (const float*)d_in[2];
    const float* qw    = (const float*)d_in[3];
    const float* qb    = (const float*)d_in[4];
    const float* kw    = (const float*)d_in[5];
    const float* kb    = (const float*)d_in[6];
    const float* vw    = (const float*)d_in[7];
    const float* vb    = (const float*)d_in[8];
    const float* ow    = (const float*)d_in[9];
    const float* ob    = (const float*)d_in[10];
    float* out = (float*)d_out;

    const int OUT_SMEM = 4*128*OS*2 + 128*4;   // 139,776 B
    cudaFuncSetAttribute(k_out, cudaFuncAttributeMaxDynamicSharedMemorySize, OUT_SMEM);

    k_qo  <<<(BB*SS*NW + 255)/256, 256>>>(x, theta);
    k_proj<<<(3*EE*32 + 255)/256, 256>>>(qw, kw, vw, proj);
    k_M   <<<HH, 96>>>(qb, kb);
    k_G   <<<EE/4, 256>>>(ow, vb, ob);
    k_attn<<<dim3(SS/128, HH, BB), 256>>>();
    k_out <<<dim3(BB*SS/128, EE/128), 256, OUT_SMEM>>>(out);
}